// round 13
// baseline (speedup 1.0000x reference)
#include <cuda_runtime.h>
#include <cuda_bf16.h>
#include <cuda_fp16.h>
#include <math.h>
#include <cstdint>

#define N_NODES 100000
#define N_EDGES 1600000
#define HIDDEN  128
#define SCALING 0.25f

// ---------------- scratch (device globals) ----------------------------------
__device__ float g_q[(size_t)N_NODES * HIDDEN / 2 + 64];
__device__ float g_k[(size_t)N_NODES * HIDDEN / 2 + 64];
__device__ float g_v[(size_t)N_NODES * HIDDEN / 2 + 64];
__device__ float g_mid[(size_t)N_NODES * HIDDEN / 2 + 64];   // fp16
__device__ int   g_colsorted[N_EDGES];
#define CNT_TILE_OFF (N_NODES + 8)
#define CNT_CTR_OFF  (N_NODES + 8 + 256)
__device__ int   g_cnt[N_NODES + 8 + 256 + 8];
__device__ int   g_start[N_NODES + 1];
__device__ int   g_cursor[N_NODES];
__device__ int   g_is64;
// weight images: [n][k] ldmatrix-swizzled; hi 16384 ushorts + lo 16384.
// g<3: bf16 (A is bf16-split fp32). g==3: fp16 (A is exact fp16 mid).
__device__ unsigned short g_wimg[4][32768];
__device__ float g_biasP[4][128];

// swizzled byte offset of (row, k) in a [128 x 128] 16-bit tile
__device__ __forceinline__ int swz_off(int row, int k) {
    return row * 256 + ((((k >> 3) ^ (row & 7)) << 4)) + ((k & 7) << 1);
}
__device__ __forceinline__ uint32_t smem_to_u32(const void* p) {
    uint32_t a;
    asm("{ .reg .u64 t; cvta.to.shared.u64 t, %1; cvt.u32.u64 %0, t; }" : "=r"(a) : "l"(p));
    return a;
}
__device__ __forceinline__ void ldsm4(uint32_t addr, uint32_t r[4]) {
    asm volatile("ldmatrix.sync.aligned.m8n8.x4.shared.b16 {%0,%1,%2,%3}, [%4];"
        : "=r"(r[0]), "=r"(r[1]), "=r"(r[2]), "=r"(r[3]) : "r"(addr));
}
__device__ __forceinline__ void mma16816(float c[4], const uint32_t a[4],
                                         uint32_t b0, uint32_t b1) {
    asm volatile("mma.sync.aligned.m16n8k16.row.col.f32.bf16.bf16.f32 "
        "{%0,%1,%2,%3}, {%4,%5,%6,%7}, {%8,%9}, {%0,%1,%2,%3};"
        : "+f"(c[0]), "+f"(c[1]), "+f"(c[2]), "+f"(c[3])
        : "r"(a[0]), "r"(a[1]), "r"(a[2]), "r"(a[3]), "r"(b0), "r"(b1));
}
__device__ __forceinline__ void mma16816h(float c[4], const uint32_t a[4],
                                          uint32_t b0, uint32_t b1) {
    asm volatile("mma.sync.aligned.m16n8k16.row.col.f32.f16.f16.f32 "
        "{%0,%1,%2,%3}, {%4,%5,%6,%7}, {%8,%9}, {%0,%1,%2,%3};"
        : "+f"(c[0]), "+f"(c[1]), "+f"(c[2]), "+f"(c[3])
        : "r"(a[0]), "r"(a[1]), "r"(a[2]), "r"(a[3]), "r"(b0), "r"(b1));
}
__device__ __forceinline__ void split2(float a, float b, unsigned& hi, unsigned& lo) {
    __nv_bfloat16 ah = __float2bfloat16(a);
    __nv_bfloat16 bh = __float2bfloat16(b);
    __nv_bfloat16 al = __float2bfloat16(a - __bfloat162float(ah));
    __nv_bfloat16 bl = __float2bfloat16(b - __bfloat162float(bh));
    hi = (unsigned)__bfloat16_as_ushort(ah) | ((unsigned)__bfloat16_as_ushort(bh) << 16);
    lo = (unsigned)__bfloat16_as_ushort(al) | ((unsigned)__bfloat16_as_ushort(bl) << 16);
}

// edge scatter (simple grid-stride loop; iterations independent, ptxas pipelines)
__device__ __forceinline__ void edge_scatter(const void* rowp, const void* colp,
                                             int E, int base, int stride) {
    int is64 = g_is64;
    for (int i = base; i < E; i += stride) {
        int r, cc;
        if (is64) {
            r  = (int)((const long long*)rowp)[i];
            cc = (int)((const long long*)colp)[i];
        } else {
            r  = ((const int*)rowp)[i];
            cc = ((const int*)colp)[i];
        }
        int pos = atomicAdd(&g_cursor[r], 1);
        g_colsorted[pos] = cc;
    }
}

// ---------------- hist (with built-in dtype detect) --------------------------
__global__ void k_hist(const void* rowp, int E) {
    __shared__ int s_is64;
    if (threadIdx.x == 0) s_is64 = 1;
    __syncthreads();
    if (threadIdx.x < 64) {
        long long v = ((const long long*)rowp)[threadIdx.x];
        if (v < 0 || v >= (1LL << 31)) atomicAnd(&s_is64, 0);
    }
    __syncthreads();
    int is64 = s_is64;
    if (blockIdx.x == 0 && threadIdx.x == 0) g_is64 = is64;
    int stride = gridDim.x * blockDim.x;
    for (int i = blockIdx.x * blockDim.x + threadIdx.x; i < E; i += stride) {
        int r = is64 ? (int)((const long long*)rowp)[i] : ((const int*)rowp)[i];
        atomicAdd(&g_cnt[r], 1);
    }
}

// ---------------- single-pass exclusive scan (decoupled lookback) ------------
__global__ void k_scan1(int n, int E) {
    __shared__ int sh[1024];
    __shared__ int s_bid, s_prev;
    unsigned* tile = (unsigned*)(g_cnt + CNT_TILE_OFF);
    const int tid = threadIdx.x;
    if (tid == 0) s_bid = atomicAdd(g_cnt + CNT_CTR_OFF, 1);
    __syncthreads();
    const int bid = s_bid;
    const int i = bid * 1024 + tid;
    int v = (i < n) ? g_cnt[i] : 0;
    sh[tid] = v;
    __syncthreads();
    for (int off = 1; off < 1024; off <<= 1) {
        int t = (tid >= off) ? sh[tid - off] : 0;
        __syncthreads();
        sh[tid] += t;
        __syncthreads();
    }
    int total = sh[1023];
    if (tid == 0) {
        unsigned flag = (bid == 0) ? 2u : 1u;
        atomicExch(&tile[bid], (flag << 30) | ((unsigned)total & 0x00FFFFFFu));
        if (bid == 0) s_prev = 0;
    }
    if (bid > 0 && tid < 32) {
        int lane = tid;
        int prev = 0;
        int look = bid - 1;
        while (true) {
            int idx = look - lane;
            unsigned st;
            do {
                st = (idx >= 0) ? atomicAdd(&tile[idx], 0u) : (2u << 30);
            } while (__any_sync(0xffffffffu, (st >> 30) == 0u));
            unsigned pmask = __ballot_sync(0xffffffffu, (st >> 30) >= 2u);
            int lim = pmask ? (__ffs(pmask) - 1) : 31;
            int val = (lane <= lim) ? (int)(st & 0x00FFFFFFu) : 0;
            #pragma unroll
            for (int o = 16; o; o >>= 1) val += __shfl_xor_sync(0xffffffffu, val, o);
            prev += val;
            if (pmask) break;
            look -= 32;
        }
        if (lane == 0) {
            s_prev = prev;
            atomicExch(&tile[bid], (2u << 30) | ((unsigned)(prev + total) & 0x00FFFFFFu));
        }
    }
    __syncthreads();
    int pre = s_prev;
    if (i < n) {
        int ex = pre + sh[tid] - v;
        g_start[i]  = ex;
        g_cursor[i] = ex;
    }
    if (i == n) g_start[n] = E;
}

// ---------------- weight conversion (once, tiny) -----------------------------
__global__ void k_wconv(const float* Wq, const float* bq, const float* Wk, const float* bk,
                        const float* Wv, const float* bv, const float* Wo, const float* bo) {
    int g = blockIdx.x, tid = threadIdx.x;
    const float* W = g == 0 ? Wq : g == 1 ? Wk : g == 2 ? Wv : Wo;
    const float* b = g == 0 ? bq : g == 1 ? bk : g == 2 ? bv : bo;
    float scale = (g == 0) ? SCALING : 1.0f;
    char* hi = (char*)g_wimg[g];
    char* lo = (char*)(g_wimg[g] + 16384);
    for (int i = tid; i < 16384; i += 256) {
        int n = i >> 7, k = i & 127;
        int sr = (g < 3) ? ((n & 15) * 8 + (n >> 4)) : n;
        int sk = (g == 3) ? ((k & 15) * 8 + (k >> 4)) : k;
        float v = W[sr * 128 + sk] * scale;
        unsigned short hbits, lbits;
        if (g == 3) {
            __half h = __float2half(v);
            __half l = __float2half(v - __half2float(h));
            hbits = __half_as_ushort(h);
            lbits = __half_as_ushort(l);
        } else {
            __nv_bfloat16 h = __float2bfloat16(v);
            __nv_bfloat16 l = __float2bfloat16(v - __bfloat162float(h));
            hbits = __bfloat16_as_ushort(h);
            lbits = __bfloat16_as_ushort(l);
        }
        int sw = swz_off(n, k);
        *(unsigned short*)(hi + sw) = hbits;
        *(unsigned short*)(lo + sw) = lbits;
    }
    if (tid < 128)
        g_biasP[g][tid] = b[(g < 3) ? ((tid & 15) * 8 + (tid >> 4)) : tid] * scale;
}

// ---------------- GEMM via mma.sync (split-precision) ------------------------
#define SMEM_MMA (2048 + 65536 + 32768)
template<bool OUTF16, bool SCAT, bool INF16>
__global__ void __launch_bounds__(256, 2)
k_mma(const void* __restrict__ Xv, int nrows, int wbase, int nst,
      void* __restrict__ o0, void* __restrict__ o1, void* __restrict__ o2,
      const void* rowp, const void* colp, int E) {
    extern __shared__ __align__(16) char smem[];
    float* sbias = (float*)smem;
    char*  As    = smem + 2048;
    char*  Bs    = smem + 2048 + 65536;
    uint32_t sbA = smem_to_u32(As);
    uint32_t sbB = smem_to_u32(Bs);

    const int tid = threadIdx.x;
    const int lane = tid & 31;
    const int wid = tid >> 5;
    const int warp_m = wid & 3;
    const int warp_n = wid >> 2;
    const int rowBase = blockIdx.x * 128;

    if (SCAT && (blockIdx.x & 1))
        edge_scatter(rowp, colp, E, blockIdx.x * blockDim.x + tid,
                     gridDim.x * blockDim.x);

    if (tid < 128)
        for (int s = 0; s < nst; s++) sbias[s * 128 + tid] = g_biasP[wbase + s][tid];

    if (INF16) {
        const char* X = (const char*)Xv;
        #pragma unroll
        for (int kk = 0; kk < 8; kk++) {
            int idx = tid + kk * 256;
            int r = idx >> 4, ch = idx & 15;
            uint4 x = make_uint4(0, 0, 0, 0);
            if (rowBase + r < nrows)
                x = *(const uint4*)(X + (size_t)(rowBase + r) * 256 + ch * 16);
            *(uint4*)(As + r * 256 + ((ch ^ (r & 7)) << 4)) = x;
        }
    } else {
        const float* X = (const float*)Xv;
        #pragma unroll
        for (int kk = 0; kk < 16; kk++) {
            int idx = tid + kk * 256;
            int r = idx >> 5, m4 = (idx & 31) << 2;
            float4 x = make_float4(0.f, 0.f, 0.f, 0.f);
            if (rowBase + r < nrows)
                x = *(const float4*)(X + (size_t)(rowBase + r) * 128 + m4);
            unsigned h01, l01, h23, l23;
            split2(x.x, x.y, h01, l01);
            split2(x.z, x.w, h23, l23);
            int sw = swz_off(r, m4);
            *(uint2*)(As + sw)         = make_uint2(h01, h23);
            *(uint2*)(As + 32768 + sw) = make_uint2(l01, l23);
        }
    }

    const int rA  = warp_m * 32 + (lane & 15);
    const int aAdd = lane >> 4;
    const int rB  = warp_n * 64 + (lane & 7) + ((lane >> 4) << 3);
    const int bAdd = (lane >> 3) & 1;

    void* outs[3] = {o0, o1, o2};
    for (int s = 0; s < nst; s++) {
        float c[2][8][4];
        #pragma unroll
        for (int mf = 0; mf < 2; mf++)
            #pragma unroll
            for (int nf = 0; nf < 8; nf++)
                #pragma unroll
                for (int t = 0; t < 4; t++) c[mf][nf][t] = 0.f;

        // ---- phase 1: B = hi image ----
        __syncthreads();
        {
            const uint4* src = (const uint4*)g_wimg[wbase + s];
            #pragma unroll
            for (int kk = 0; kk < 8; kk++)
                ((uint4*)Bs)[tid + kk * 256] = src[tid + kk * 256];
        }
        __syncthreads();
        #pragma unroll
        for (int ks = 0; ks < 8; ks++) {
            const int chA = 2 * ks + aAdd;
            const int chB = 2 * ks + bAdd;
            uint32_t Ah[2][4], Al[2][4];
            #pragma unroll
            for (int mf = 0; mf < 2; mf++) {
                int row = rA + mf * 16;
                uint32_t addr = sbA + row * 256 + (((chA ^ (row & 7))) << 4);
                ldsm4(addr, Ah[mf]);
                if (!INF16) ldsm4(addr + 32768, Al[mf]);
            }
            #pragma unroll
            for (int nf16 = 0; nf16 < 4; nf16++) {
                int row = rB + nf16 * 16;
                uint32_t addr = sbB + row * 256 + (((chB ^ (row & 7))) << 4);
                uint32_t Bh[4];
                ldsm4(addr, Bh);
                #pragma unroll
                for (int mf = 0; mf < 2; mf++) {
                    if (INF16) {
                        mma16816h(c[mf][2 * nf16],     Ah[mf], Bh[0], Bh[1]);
                        mma16816h(c[mf][2 * nf16 + 1], Ah[mf], Bh[2], Bh[3]);
                    } else {
                        mma16816(c[mf][2 * nf16],     Ah[mf], Bh[0], Bh[1]);
                        mma16816(c[mf][2 * nf16 + 1], Ah[mf], Bh[2], Bh[3]);
                        mma16816(c[mf][2 * nf16],     Al[mf], Bh[0], Bh[1]);
                        mma16816(c[mf][2 * nf16 + 1], Al[mf], Bh[2], Bh[3]);
                    }
                }
            }
        }

        // ---- phase 2: B = lo image ----
        __syncthreads();
        {
            const uint4* src = (const uint4*)(g_wimg[wbase + s] + 16384);
            #pragma unroll
            for (int kk = 0; kk < 8; kk++)
                ((uint4*)Bs)[tid + kk * 256] = src[tid + kk * 256];
        }
        __syncthreads();
        #pragma unroll
        for (int ks = 0; ks < 8; ks++) {
            const int chA = 2 * ks + aAdd;
            const int chB = 2 * ks + bAdd;
            uint32_t Ah[2][4];
            #pragma unroll
            for (int mf = 0; mf < 2; mf++) {
                int row = rA + mf * 16;
                ldsm4(sbA + row * 256 + (((chA ^ (row & 7))) << 4), Ah[mf]);
            }
            #pragma unroll
            for (int nf16 = 0; nf16 < 4; nf16++) {
                int row = rB + nf16 * 16;
                uint32_t Bl[4];
                ldsm4(sbB + row * 256 + (((chB ^ (row & 7))) << 4), Bl);
                #pragma unroll
                for (int mf = 0; mf < 2; mf++) {
                    if (INF16) {
                        mma16816h(c[mf][2 * nf16],     Ah[mf], Bl[0], Bl[1]);
                        mma16816h(c[mf][2 * nf16 + 1], Ah[mf], Bl[2], Bl[3]);
                    } else {
                        mma16816(c[mf][2 * nf16],     Ah[mf], Bl[0], Bl[1]);
                        mma16816(c[mf][2 * nf16 + 1], Ah[mf], Bl[2], Bl[3]);
                    }
                }
            }
        }

        // epilogue
        #pragma unroll
        for (int mf = 0; mf < 2; mf++) {
            int m0 = rowBase + warp_m * 32 + mf * 16 + (lane >> 2);
            #pragma unroll
            for (int nf = 0; nf < 8; nf++) {
                int n = warp_n * 64 + nf * 8 + ((lane & 3) << 1);
                float b0 = sbias[s * 128 + n], b1 = sbias[s * 128 + n + 1];
                if (OUTF16) {
                    __half2* O = (__half2*)outs[s];
                    if (m0 < nrows)
                        O[(size_t)m0 * 64 + (n >> 1)] =
                            __floats2half2_rn(c[mf][nf][0] + b0, c[mf][nf][1] + b1);
                    if (m0 + 8 < nrows)
                        O[(size_t)(m0 + 8) * 64 + (n >> 1)] =
                            __floats2half2_rn(c[mf][nf][2] + b0, c[mf][nf][3] + b1);
                } else {
                    float* O = (float*)outs[s];
                    if (m0 < nrows)
                        *(float2*)(O + (size_t)m0 * 128 + n) =
                            make_float2(c[mf][nf][0] + b0, c[mf][nf][1] + b1);
                    if (m0 + 8 < nrows)
                        *(float2*)(O + (size_t)(m0 + 8) * 128 + n) =
                            make_float2(c[mf][nf][2] + b0, c[mf][nf][3] + b1);
                }
            }
        }
    }

    if (SCAT && !(blockIdx.x & 1))
        edge_scatter(rowp, colp, E, blockIdx.x * blockDim.x + tid,
                     gridDim.x * blockDim.x);
}

// ---------------- per-row attention (one warp per destination node) ---------
// q/k/v fp16 HEAD-MAJOR; mid fp16. Software-pipelined batch-4: batch b+1's 8
// gathers are issued before batch b's compute (MLP of batch-8, registers of
// batch-4 — avoids the R10 spill).
__device__ __forceinline__ void attn_batch4(const uint2 kr[4], const uint2 vr[4],
                                            float2 q01, float2 q23,
                                            float& a0, float& a1, float& a2,
                                            float& a3, float& s) {
    float p[4];
    #pragma unroll
    for (int j = 0; j < 4; j++) {
        float2 k01 = __half22float2(*reinterpret_cast<const __half2*>(&kr[j].x));
        float2 k23 = __half22float2(*reinterpret_cast<const __half2*>(&kr[j].y));
        float t = q01.x * k01.x;
        t = fmaf(q01.y, k01.y, t);
        t = fmaf(q23.x, k23.x, t);
        t = fmaf(q23.y, k23.y, t);
        p[j] = t;
    }
    #pragma unroll
    for (int j = 0; j < 4; j++) p[j] += __shfl_xor_sync(0xffffffffu, p[j], 1);
    #pragma unroll
    for (int j = 0; j < 4; j++) p[j] += __shfl_xor_sync(0xffffffffu, p[j], 2);
    #pragma unroll
    for (int j = 0; j < 4; j++) {
        float ex = __expf(p[j]);
        float2 v01 = __half22float2(*reinterpret_cast<const __half2*>(&vr[j].x));
        float2 v23 = __half22float2(*reinterpret_cast<const __half2*>(&vr[j].y));
        s += ex;
        a0 = fmaf(ex, v01.x, a0);
        a1 = fmaf(ex, v01.y, a1);
        a2 = fmaf(ex, v23.x, a2);
        a3 = fmaf(ex, v23.y, a3);
    }
}

__global__ void k_attn(int n) {
    int gw = (blockIdx.x * blockDim.x + threadIdx.x) >> 5;
    int lane = threadIdx.x & 31;
    if (gw >= n) return;
    int s0 = g_start[gw], s1 = g_start[gw + 1];
    const __half* qh = (const __half*)g_q;
    const __half* kh = (const __half*)g_k;
    const __half* vh = (const __half*)g_v;

    uint2 qr = *(const uint2*)(qh + (size_t)gw * 128 + lane * 4);
    float2 q01 = __half22float2(*reinterpret_cast<__half2*>(&qr.x));
    float2 q23 = __half22float2(*reinterpret_cast<__half2*>(&qr.y));

    float a0 = 0.f, a1 = 0.f, a2 = 0.f, a3 = 0.f, s = 0.f;

    int e = s0;
    int nfull = (s1 - s0) >> 2;
    uint2 kr[4], vr[4];
    if (nfull > 0) {
        #pragma unroll
        for (int j = 0; j < 4; j++) {
            int c = g_colsorted[e + j];
            kr[j] = *(const uint2*)(kh + (size_t)c * 128 + lane * 4);
            vr[j] = *(const uint2*)(vh + (size_t)c * 128 + lane * 4);
        }
    }
    for (int b = 1; b < nfull; b++) {
        uint2 kn[4], vn[4];
        int e2 = e + 4;
        #pragma unroll
        for (int j = 0; j < 4; j++) {
            int c = g_colsorted[e2 + j];
            kn[j] = *(const uint2*)(kh + (size_t)c * 128 + lane * 4);
            vn[j] = *(const uint2*)(vh + (size_t)c * 128 + lane * 4);
        }
        attn_batch4(kr, vr, q01, q23, a0, a1, a2, a3, s);
        #pragma unroll
        for (int j = 0; j < 4; j++) { kr[j] = kn[j]; vr[j] = vn[j]; }
        e = e2;
    }
    if (nfull > 0) {
        attn_batch4(kr, vr, q01, q23, a0, a1, a2, a3, s);
        e += 4;
    }
    for (; e < s1; e++) {
        int c = g_colsorted[e];
        uint2 k1 = *(const uint2*)(kh + (size_t)c * 128 + lane * 4);
        uint2 v1 = *(const uint2*)(vh + (size_t)c * 128 + lane * 4);
        float2 k01 = __half22float2(*reinterpret_cast<__half2*>(&k1.x));
        float2 k23 = __half22float2(*reinterpret_cast<__half2*>(&k1.y));
        float2 v01 = __half22float2(*reinterpret_cast<__half2*>(&v1.x));
        float2 v23 = __half22float2(*reinterpret_cast<__half2*>(&v1.y));
        float p = q01.x * k01.x;
        p = fmaf(q01.y, k01.y, p);
        p = fmaf(q23.x, k23.x, p);
        p = fmaf(q23.y, k23.y, p);
        p += __shfl_xor_sync(0xffffffffu, p, 1);
        p += __shfl_xor_sync(0xffffffffu, p, 2);
        float ex = __expf(p);
        s += ex;
        a0 = fmaf(ex, v01.x, a0);
        a1 = fmaf(ex, v01.y, a1);
        a2 = fmaf(ex, v23.x, a2);
        a3 = fmaf(ex, v23.y, a3);
    }
    float inv = (s > 0.f) ? 1.f / s : 0.f;
    __half2* mh = (__half2*)g_mid;
    mh[(size_t)gw * 64 + lane * 2 + 0] = __floats2half2_rn(a0 * inv, a1 * inv);
    mh[(size_t)gw * 64 + lane * 2 + 1] = __floats2half2_rn(a2 * inv, a3 * inv);
}

// ---------------- launch ------------------------------------------------------
extern "C" void kernel_launch(void* const* d_in, const int* in_sizes, int n_in,
                              void* d_out, int out_size) {
    const float* h    = (const float*)d_in[0];
    const void*  rowp = d_in[1];
    const void*  colp = d_in[2];
    const float* Wq = (const float*)d_in[3];
    const float* bq = (const float*)d_in[4];
    const float* Wk = (const float*)d_in[5];
    const float* bk = (const float*)d_in[6];
    const float* Wv = (const float*)d_in[7];
    const float* bv = (const float*)d_in[8];
    const float* Wo = (const float*)d_in[9];
    const float* bo = (const float*)d_in[10];
    float* out = (float*)d_out;

    int N = in_sizes[0] / HIDDEN;
    int E = in_sizes[1];

    cudaFuncSetAttribute((const void*)k_mma<true, true, false>,
                         cudaFuncAttributeMaxDynamicSharedMemorySize, SMEM_MMA);
    cudaFuncSetAttribute((const void*)k_mma<false, false, true>,
                         cudaFuncAttributeMaxDynamicSharedMemorySize, SMEM_MMA);

    void *pq, *pk, *pv, *pmid, *pcnt;
    cudaGetSymbolAddress(&pq, g_q);
    cudaGetSymbolAddress(&pk, g_k);
    cudaGetSymbolAddress(&pv, g_v);
    cudaGetSymbolAddress(&pmid, g_mid);
    cudaGetSymbolAddress(&pcnt, g_cnt);

    int gb = (N + 127) / 128;
    int nb = (N + 1 + 1023) / 1024;

    cudaMemsetAsync(pcnt, 0, sizeof(g_cnt));                                   // 0
    k_hist<<<1024, 256>>>(rowp, E);                                            // 1
    k_scan1<<<nb, 1024>>>(N, E);                                               // 2
    k_wconv<<<4, 256>>>(Wq, bq, Wk, bk, Wv, bv, Wo, bo);                       // 3
    k_mma<true, true, false><<<gb, 256, SMEM_MMA>>>(h, N, 0, 3, pq, pk, pv,
                                                    rowp, colp, E);            // 4 <- profiled
    k_attn<<<(N + 7) / 8, 256>>>(N);                                           // 5
    k_mma<false, false, true><<<gb, 256, SMEM_MMA>>>(pmid, N, 3, 1,
                                                     out, 0, 0, 0, 0, 0);      // 6
}

// round 14
// speedup vs baseline: 1.0924x; 1.0924x over previous
#include <cuda_runtime.h>
#include <cuda_bf16.h>
#include <cuda_fp16.h>
#include <math.h>
#include <cstdint>

#define N_NODES 100000
#define N_EDGES 1600000
#define HIDDEN  128
#define SCALING 0.25f

// ---------------- scratch (device globals) ----------------------------------
__device__ float g_q[(size_t)N_NODES * HIDDEN / 2 + 64];
__device__ float g_k[(size_t)N_NODES * HIDDEN / 2 + 64];
__device__ float g_v[(size_t)N_NODES * HIDDEN / 2 + 64];
__device__ float g_mid[(size_t)N_NODES * HIDDEN / 2 + 64];   // fp16
__device__ int   g_colsorted[N_EDGES];
#define CNT_TILE_OFF (N_NODES + 8)
#define CNT_CTR_OFF  (N_NODES + 8 + 256)
__device__ int   g_cnt[N_NODES + 8 + 256 + 8];
__device__ int   g_start[N_NODES + 1];
__device__ int   g_cursor[N_NODES];
__device__ int   g_is64;
// weight images: [n][k] ldmatrix-swizzled; hi 16384 ushorts + lo 16384.
// g<3: bf16 (A is bf16-split fp32). g==3: fp16 (A is exact fp16 mid).
__device__ unsigned short g_wimg[4][32768];
__device__ float g_biasP[4][128];

// swizzled byte offset of (row, k) in a [128 x 128] 16-bit tile
__device__ __forceinline__ int swz_off(int row, int k) {
    return row * 256 + ((((k >> 3) ^ (row & 7)) << 4)) + ((k & 7) << 1);
}
__device__ __forceinline__ uint32_t smem_to_u32(const void* p) {
    uint32_t a;
    asm("{ .reg .u64 t; cvta.to.shared.u64 t, %1; cvt.u32.u64 %0, t; }" : "=r"(a) : "l"(p));
    return a;
}
__device__ __forceinline__ void ldsm4(uint32_t addr, uint32_t r[4]) {
    asm volatile("ldmatrix.sync.aligned.m8n8.x4.shared.b16 {%0,%1,%2,%3}, [%4];"
        : "=r"(r[0]), "=r"(r[1]), "=r"(r[2]), "=r"(r[3]) : "r"(addr));
}
__device__ __forceinline__ void mma16816(float c[4], const uint32_t a[4],
                                         uint32_t b0, uint32_t b1) {
    asm volatile("mma.sync.aligned.m16n8k16.row.col.f32.bf16.bf16.f32 "
        "{%0,%1,%2,%3}, {%4,%5,%6,%7}, {%8,%9}, {%0,%1,%2,%3};"
        : "+f"(c[0]), "+f"(c[1]), "+f"(c[2]), "+f"(c[3])
        : "r"(a[0]), "r"(a[1]), "r"(a[2]), "r"(a[3]), "r"(b0), "r"(b1));
}
__device__ __forceinline__ void mma16816h(float c[4], const uint32_t a[4],
                                          uint32_t b0, uint32_t b1) {
    asm volatile("mma.sync.aligned.m16n8k16.row.col.f32.f16.f16.f32 "
        "{%0,%1,%2,%3}, {%4,%5,%6,%7}, {%8,%9}, {%0,%1,%2,%3};"
        : "+f"(c[0]), "+f"(c[1]), "+f"(c[2]), "+f"(c[3])
        : "r"(a[0]), "r"(a[1]), "r"(a[2]), "r"(a[3]), "r"(b0), "r"(b1));
}
__device__ __forceinline__ void split2(float a, float b, unsigned& hi, unsigned& lo) {
    __nv_bfloat16 ah = __float2bfloat16(a);
    __nv_bfloat16 bh = __float2bfloat16(b);
    __nv_bfloat16 al = __float2bfloat16(a - __bfloat162float(ah));
    __nv_bfloat16 bl = __float2bfloat16(b - __bfloat162float(bh));
    hi = (unsigned)__bfloat16_as_ushort(ah) | ((unsigned)__bfloat16_as_ushort(bh) << 16);
    lo = (unsigned)__bfloat16_as_ushort(al) | ((unsigned)__bfloat16_as_ushort(bl) << 16);
}

// ---------------- hist (with built-in dtype detect) --------------------------
__global__ void k_hist(const void* rowp, int E) {
    __shared__ int s_is64;
    if (threadIdx.x == 0) s_is64 = 1;
    __syncthreads();
    if (threadIdx.x < 64) {
        long long v = ((const long long*)rowp)[threadIdx.x];
        if (v < 0 || v >= (1LL << 31)) atomicAnd(&s_is64, 0);
    }
    __syncthreads();
    int is64 = s_is64;
    if (blockIdx.x == 0 && threadIdx.x == 0) g_is64 = is64;
    int stride = gridDim.x * blockDim.x;
    for (int i = blockIdx.x * blockDim.x + threadIdx.x; i < E; i += stride) {
        int r = is64 ? (int)((const long long*)rowp)[i] : ((const int*)rowp)[i];
        atomicAdd(&g_cnt[r], 1);
    }
}

// ---------------- single-pass exclusive scan (decoupled lookback) ------------
__global__ void k_scan1(int n, int E) {
    __shared__ int sh[1024];
    __shared__ int s_bid, s_prev;
    unsigned* tile = (unsigned*)(g_cnt + CNT_TILE_OFF);
    const int tid = threadIdx.x;
    if (tid == 0) s_bid = atomicAdd(g_cnt + CNT_CTR_OFF, 1);
    __syncthreads();
    const int bid = s_bid;
    const int i = bid * 1024 + tid;
    int v = (i < n) ? g_cnt[i] : 0;
    sh[tid] = v;
    __syncthreads();
    for (int off = 1; off < 1024; off <<= 1) {
        int t = (tid >= off) ? sh[tid - off] : 0;
        __syncthreads();
        sh[tid] += t;
        __syncthreads();
    }
    int total = sh[1023];
    if (tid == 0) {
        unsigned flag = (bid == 0) ? 2u : 1u;
        atomicExch(&tile[bid], (flag << 30) | ((unsigned)total & 0x00FFFFFFu));
        if (bid == 0) s_prev = 0;
    }
    if (bid > 0 && tid < 32) {
        int lane = tid;
        int prev = 0;
        int look = bid - 1;
        while (true) {
            int idx = look - lane;
            unsigned st;
            do {
                st = (idx >= 0) ? atomicAdd(&tile[idx], 0u) : (2u << 30);
            } while (__any_sync(0xffffffffu, (st >> 30) == 0u));
            unsigned pmask = __ballot_sync(0xffffffffu, (st >> 30) >= 2u);
            int lim = pmask ? (__ffs(pmask) - 1) : 31;
            int val = (lane <= lim) ? (int)(st & 0x00FFFFFFu) : 0;
            #pragma unroll
            for (int o = 16; o; o >>= 1) val += __shfl_xor_sync(0xffffffffu, val, o);
            prev += val;
            if (pmask) break;
            look -= 32;
        }
        if (lane == 0) {
            s_prev = prev;
            atomicExch(&tile[bid], (2u << 30) | ((unsigned)(prev + total) & 0x00FFFFFFu));
        }
    }
    __syncthreads();
    int pre = s_prev;
    if (i < n) {
        int ex = pre + sh[tid] - v;
        g_start[i]  = ex;
        g_cursor[i] = ex;
    }
    if (i == n) g_start[n] = E;
}

// ---------------- standalone edge scatter -------------------------------------
__global__ void k_scat(const void* rowp, const void* colp, int E) {
    int is64 = g_is64;
    int stride = gridDim.x * blockDim.x;
    for (int i = blockIdx.x * blockDim.x + threadIdx.x; i < E; i += stride) {
        int r, cc;
        if (is64) {
            r  = (int)((const long long*)rowp)[i];
            cc = (int)((const long long*)colp)[i];
        } else {
            r  = ((const int*)rowp)[i];
            cc = ((const int*)colp)[i];
        }
        int pos = atomicAdd(&g_cursor[r], 1);
        g_colsorted[pos] = cc;
    }
}

// ---------------- weight conversion (once, tiny) -----------------------------
__global__ void k_wconv(const float* Wq, const float* bq, const float* Wk, const float* bk,
                        const float* Wv, const float* bv, const float* Wo, const float* bo) {
    int g = blockIdx.x, tid = threadIdx.x;
    const float* W = g == 0 ? Wq : g == 1 ? Wk : g == 2 ? Wv : Wo;
    const float* b = g == 0 ? bq : g == 1 ? bk : g == 2 ? bv : bo;
    float scale = (g == 0) ? SCALING : 1.0f;
    char* hi = (char*)g_wimg[g];
    char* lo = (char*)(g_wimg[g] + 16384);
    for (int i = tid; i < 16384; i += 256) {
        int n = i >> 7, k = i & 127;
        int sr = (g < 3) ? ((n & 15) * 8 + (n >> 4)) : n;
        int sk = (g == 3) ? ((k & 15) * 8 + (k >> 4)) : k;
        float v = W[sr * 128 + sk] * scale;
        unsigned short hbits, lbits;
        if (g == 3) {
            __half h = __float2half(v);
            __half l = __float2half(v - __half2float(h));
            hbits = __half_as_ushort(h);
            lbits = __half_as_ushort(l);
        } else {
            __nv_bfloat16 h = __float2bfloat16(v);
            __nv_bfloat16 l = __float2bfloat16(v - __bfloat162float(h));
            hbits = __bfloat16_as_ushort(h);
            lbits = __bfloat16_as_ushort(l);
        }
        int sw = swz_off(n, k);
        *(unsigned short*)(hi + sw) = hbits;
        *(unsigned short*)(lo + sw) = lbits;
    }
    if (tid < 128)
        g_biasP[g][tid] = b[(g < 3) ? ((tid & 15) * 8 + (tid >> 4)) : tid] * scale;
}

// ---------------- GEMM via mma.sync (split-precision) ------------------------
#define SMEM_MMA (2048 + 65536 + 32768)
template<bool OUTF16, bool INF16>
__global__ void __launch_bounds__(256, 2)
k_mma(const void* __restrict__ Xv, int nrows, int wbase, int nst,
      void* __restrict__ o0, void* __restrict__ o1, void* __restrict__ o2) {
    extern __shared__ __align__(16) char smem[];
    float* sbias = (float*)smem;
    char*  As    = smem + 2048;
    char*  Bs    = smem + 2048 + 65536;
    uint32_t sbA = smem_to_u32(As);
    uint32_t sbB = smem_to_u32(Bs);

    const int tid = threadIdx.x;
    const int lane = tid & 31;
    const int wid = tid >> 5;
    const int warp_m = wid & 3;
    const int warp_n = wid >> 2;
    const int rowBase = blockIdx.x * 128;

    if (tid < 128)
        for (int s = 0; s < nst; s++) sbias[s * 128 + tid] = g_biasP[wbase + s][tid];

    if (INF16) {
        const char* X = (const char*)Xv;
        #pragma unroll
        for (int kk = 0; kk < 8; kk++) {
            int idx = tid + kk * 256;
            int r = idx >> 4, ch = idx & 15;
            uint4 x = make_uint4(0, 0, 0, 0);
            if (rowBase + r < nrows)
                x = *(const uint4*)(X + (size_t)(rowBase + r) * 256 + ch * 16);
            *(uint4*)(As + r * 256 + ((ch ^ (r & 7)) << 4)) = x;
        }
    } else {
        const float* X = (const float*)Xv;
        #pragma unroll
        for (int kk = 0; kk < 16; kk++) {
            int idx = tid + kk * 256;
            int r = idx >> 5, m4 = (idx & 31) << 2;
            float4 x = make_float4(0.f, 0.f, 0.f, 0.f);
            if (rowBase + r < nrows)
                x = *(const float4*)(X + (size_t)(rowBase + r) * 128 + m4);
            unsigned h01, l01, h23, l23;
            split2(x.x, x.y, h01, l01);
            split2(x.z, x.w, h23, l23);
            int sw = swz_off(r, m4);
            *(uint2*)(As + sw)         = make_uint2(h01, h23);
            *(uint2*)(As + 32768 + sw) = make_uint2(l01, l23);
        }
    }

    const int rA  = warp_m * 32 + (lane & 15);
    const int aAdd = lane >> 4;
    const int rB  = warp_n * 64 + (lane & 7) + ((lane >> 4) << 3);
    const int bAdd = (lane >> 3) & 1;

    void* outs[3] = {o0, o1, o2};
    for (int s = 0; s < nst; s++) {
        float c[2][8][4];
        #pragma unroll
        for (int mf = 0; mf < 2; mf++)
            #pragma unroll
            for (int nf = 0; nf < 8; nf++)
                #pragma unroll
                for (int t = 0; t < 4; t++) c[mf][nf][t] = 0.f;

        // ---- phase 1: B = hi image ----
        __syncthreads();
        {
            const uint4* src = (const uint4*)g_wimg[wbase + s];
            #pragma unroll
            for (int kk = 0; kk < 8; kk++)
                ((uint4*)Bs)[tid + kk * 256] = src[tid + kk * 256];
        }
        __syncthreads();
        #pragma unroll
        for (int ks = 0; ks < 8; ks++) {
            const int chA = 2 * ks + aAdd;
            const int chB = 2 * ks + bAdd;
            uint32_t Ah[2][4], Al[2][4];
            #pragma unroll
            for (int mf = 0; mf < 2; mf++) {
                int row = rA + mf * 16;
                uint32_t addr = sbA + row * 256 + (((chA ^ (row & 7))) << 4);
                ldsm4(addr, Ah[mf]);
                if (!INF16) ldsm4(addr + 32768, Al[mf]);
            }
            #pragma unroll
            for (int nf16 = 0; nf16 < 4; nf16++) {
                int row = rB + nf16 * 16;
                uint32_t addr = sbB + row * 256 + (((chB ^ (row & 7))) << 4);
                uint32_t Bh[4];
                ldsm4(addr, Bh);
                #pragma unroll
                for (int mf = 0; mf < 2; mf++) {
                    if (INF16) {
                        mma16816h(c[mf][2 * nf16],     Ah[mf], Bh[0], Bh[1]);
                        mma16816h(c[mf][2 * nf16 + 1], Ah[mf], Bh[2], Bh[3]);
                    } else {
                        mma16816(c[mf][2 * nf16],     Ah[mf], Bh[0], Bh[1]);
                        mma16816(c[mf][2 * nf16 + 1], Ah[mf], Bh[2], Bh[3]);
                        mma16816(c[mf][2 * nf16],     Al[mf], Bh[0], Bh[1]);
                        mma16816(c[mf][2 * nf16 + 1], Al[mf], Bh[2], Bh[3]);
                    }
                }
            }
        }

        // ---- phase 2: B = lo image ----
        __syncthreads();
        {
            const uint4* src = (const uint4*)(g_wimg[wbase + s] + 16384);
            #pragma unroll
            for (int kk = 0; kk < 8; kk++)
                ((uint4*)Bs)[tid + kk * 256] = src[tid + kk * 256];
        }
        __syncthreads();
        #pragma unroll
        for (int ks = 0; ks < 8; ks++) {
            const int chA = 2 * ks + aAdd;
            const int chB = 2 * ks + bAdd;
            uint32_t Ah[2][4];
            #pragma unroll
            for (int mf = 0; mf < 2; mf++) {
                int row = rA + mf * 16;
                ldsm4(sbA + row * 256 + (((chA ^ (row & 7))) << 4), Ah[mf]);
            }
            #pragma unroll
            for (int nf16 = 0; nf16 < 4; nf16++) {
                int row = rB + nf16 * 16;
                uint32_t Bl[4];
                ldsm4(sbB + row * 256 + (((chB ^ (row & 7))) << 4), Bl);
                #pragma unroll
                for (int mf = 0; mf < 2; mf++) {
                    if (INF16) {
                        mma16816h(c[mf][2 * nf16],     Ah[mf], Bl[0], Bl[1]);
                        mma16816h(c[mf][2 * nf16 + 1], Ah[mf], Bl[2], Bl[3]);
                    } else {
                        mma16816(c[mf][2 * nf16],     Ah[mf], Bl[0], Bl[1]);
                        mma16816(c[mf][2 * nf16 + 1], Ah[mf], Bl[2], Bl[3]);
                    }
                }
            }
        }

        // epilogue
        #pragma unroll
        for (int mf = 0; mf < 2; mf++) {
            int m0 = rowBase + warp_m * 32 + mf * 16 + (lane >> 2);
            #pragma unroll
            for (int nf = 0; nf < 8; nf++) {
                int n = warp_n * 64 + nf * 8 + ((lane & 3) << 1);
                float b0 = sbias[s * 128 + n], b1 = sbias[s * 128 + n + 1];
                if (OUTF16) {
                    __half2* O = (__half2*)outs[s];
                    if (m0 < nrows)
                        O[(size_t)m0 * 64 + (n >> 1)] =
                            __floats2half2_rn(c[mf][nf][0] + b0, c[mf][nf][1] + b1);
                    if (m0 + 8 < nrows)
                        O[(size_t)(m0 + 8) * 64 + (n >> 1)] =
                            __floats2half2_rn(c[mf][nf][2] + b0, c[mf][nf][3] + b1);
                } else {
                    float* O = (float*)outs[s];
                    if (m0 < nrows)
                        *(float2*)(O + (size_t)m0 * 128 + n) =
                            make_float2(c[mf][nf][0] + b0, c[mf][nf][1] + b1);
                    if (m0 + 8 < nrows)
                        *(float2*)(O + (size_t)(m0 + 8) * 128 + n) =
                            make_float2(c[mf][nf][2] + b0, c[mf][nf][3] + b1);
                }
            }
        }
    }
}

// ---------------- per-row attention (one warp per destination node) ---------
// q/k/v fp16 HEAD-MAJOR; mid fp16. Simple batch-4 loop (R11 config — best).
__global__ void k_attn(int n) {
    int gw = (blockIdx.x * blockDim.x + threadIdx.x) >> 5;
    int lane = threadIdx.x & 31;
    if (gw >= n) return;
    int s0 = g_start[gw], s1 = g_start[gw + 1];
    const __half* qh = (const __half*)g_q;
    const __half* kh = (const __half*)g_k;
    const __half* vh = (const __half*)g_v;

    uint2 qr = *(const uint2*)(qh + (size_t)gw * 128 + lane * 4);
    float2 q01 = __half22float2(*reinterpret_cast<__half2*>(&qr.x));
    float2 q23 = __half22float2(*reinterpret_cast<__half2*>(&qr.y));

    float a0 = 0.f, a1 = 0.f, a2 = 0.f, a3 = 0.f, s = 0.f;

    int e = s0;
    for (; e + 4 <= s1; e += 4) {
        int c0 = g_colsorted[e + 0];
        int c1 = g_colsorted[e + 1];
        int c2 = g_colsorted[e + 2];
        int c3 = g_colsorted[e + 3];
        uint2 kr0 = *(const uint2*)(kh + (size_t)c0 * 128 + lane * 4);
        uint2 kr1 = *(const uint2*)(kh + (size_t)c1 * 128 + lane * 4);
        uint2 kr2 = *(const uint2*)(kh + (size_t)c2 * 128 + lane * 4);
        uint2 kr3 = *(const uint2*)(kh + (size_t)c3 * 128 + lane * 4);
        uint2 vr0 = *(const uint2*)(vh + (size_t)c0 * 128 + lane * 4);
        uint2 vr1 = *(const uint2*)(vh + (size_t)c1 * 128 + lane * 4);
        uint2 vr2 = *(const uint2*)(vh + (size_t)c2 * 128 + lane * 4);
        uint2 vr3 = *(const uint2*)(vh + (size_t)c3 * 128 + lane * 4);

        uint2 krs[4] = {kr0, kr1, kr2, kr3};
        uint2 vrs[4] = {vr0, vr1, vr2, vr3};
        float p[4];
        #pragma unroll
        for (int j = 0; j < 4; j++) {
            float2 k01 = __half22float2(*reinterpret_cast<__half2*>(&krs[j].x));
            float2 k23 = __half22float2(*reinterpret_cast<__half2*>(&krs[j].y));
            float t = q01.x * k01.x;
            t = fmaf(q01.y, k01.y, t);
            t = fmaf(q23.x, k23.x, t);
            t = fmaf(q23.y, k23.y, t);
            p[j] = t;
        }
        #pragma unroll
        for (int j = 0; j < 4; j++) p[j] += __shfl_xor_sync(0xffffffffu, p[j], 1);
        #pragma unroll
        for (int j = 0; j < 4; j++) p[j] += __shfl_xor_sync(0xffffffffu, p[j], 2);
        #pragma unroll
        for (int j = 0; j < 4; j++) {
            float ex = __expf(p[j]);
            float2 v01 = __half22float2(*reinterpret_cast<__half2*>(&vrs[j].x));
            float2 v23 = __half22float2(*reinterpret_cast<__half2*>(&vrs[j].y));
            s += ex;
            a0 = fmaf(ex, v01.x, a0);
            a1 = fmaf(ex, v01.y, a1);
            a2 = fmaf(ex, v23.x, a2);
            a3 = fmaf(ex, v23.y, a3);
        }
    }
    for (; e < s1; e++) {
        int c = g_colsorted[e];
        uint2 kr = *(const uint2*)(kh + (size_t)c * 128 + lane * 4);
        uint2 vr = *(const uint2*)(vh + (size_t)c * 128 + lane * 4);
        float2 k01 = __half22float2(*reinterpret_cast<__half2*>(&kr.x));
        float2 k23 = __half22float2(*reinterpret_cast<__half2*>(&kr.y));
        float2 v01 = __half22float2(*reinterpret_cast<__half2*>(&vr.x));
        float2 v23 = __half22float2(*reinterpret_cast<__half2*>(&vr.y));
        float p = q01.x * k01.x;
        p = fmaf(q01.y, k01.y, p);
        p = fmaf(q23.x, k23.x, p);
        p = fmaf(q23.y, k23.y, p);
        p += __shfl_xor_sync(0xffffffffu, p, 1);
        p += __shfl_xor_sync(0xffffffffu, p, 2);
        float ex = __expf(p);
        s += ex;
        a0 = fmaf(ex, v01.x, a0);
        a1 = fmaf(ex, v01.y, a1);
        a2 = fmaf(ex, v23.x, a2);
        a3 = fmaf(ex, v23.y, a3);
    }
    float inv = (s > 0.f) ? 1.f / s : 0.f;
    __half2* mh = (__half2*)g_mid;
    mh[(size_t)gw * 64 + lane * 2 + 0] = __floats2half2_rn(a0 * inv, a1 * inv);
    mh[(size_t)gw * 64 + lane * 2 + 1] = __floats2half2_rn(a2 * inv, a3 * inv);
}

// ---------------- launch ------------------------------------------------------
extern "C" void kernel_launch(void* const* d_in, const int* in_sizes, int n_in,
                              void* d_out, int out_size) {
    const float* h    = (const float*)d_in[0];
    const void*  rowp = d_in[1];
    const void*  colp = d_in[2];
    const float* Wq = (const float*)d_in[3];
    const float* bq = (const float*)d_in[4];
    const float* Wk = (const float*)d_in[5];
    const float* bk = (const float*)d_in[6];
    const float* Wv = (const float*)d_in[7];
    const float* bv = (const float*)d_in[8];
    const float* Wo = (const float*)d_in[9];
    const float* bo = (const float*)d_in[10];
    float* out = (float*)d_out;

    int N = in_sizes[0] / HIDDEN;
    int E = in_sizes[1];

    cudaFuncSetAttribute((const void*)k_mma<true, false>,
                         cudaFuncAttributeMaxDynamicSharedMemorySize, SMEM_MMA);
    cudaFuncSetAttribute((const void*)k_mma<false, true>,
                         cudaFuncAttributeMaxDynamicSharedMemorySize, SMEM_MMA);

    void *pq, *pk, *pv, *pmid, *pcnt;
    cudaGetSymbolAddress(&pq, g_q);
    cudaGetSymbolAddress(&pk, g_k);
    cudaGetSymbolAddress(&pv, g_v);
    cudaGetSymbolAddress(&pmid, g_mid);
    cudaGetSymbolAddress(&pcnt, g_cnt);

    int gb = (N + 127) / 128;
    int nb = (N + 1 + 1023) / 1024;

    cudaMemsetAsync(pcnt, 0, sizeof(g_cnt));                                   // 0
    k_hist<<<1024, 256>>>(rowp, E);                                            // 1
    k_scan1<<<nb, 1024>>>(N, E);                                               // 2
    k_wconv<<<4, 256>>>(Wq, bq, Wk, bk, Wv, bv, Wo, bo);                       // 3
    k_mma<true, false><<<gb, 256, SMEM_MMA>>>(h, N, 0, 3, pq, pk, pv);         // 4 <- profiled
    k_scat<<<1024, 256>>>(rowp, colp, E);                                      // 5
    k_attn<<<(N + 7) / 8, 256>>>(N);                                           // 6
    k_mma<false, true><<<gb, 256, SMEM_MMA>>>(pmid, N, 3, 1, out, 0, 0);       // 7
}

// round 15
// speedup vs baseline: 1.3453x; 1.2315x over previous
#include <cuda_runtime.h>
#include <cuda_fp16.h>
#include <math.h>
#include <cstdint>

#define N_NODES 100000
#define N_EDGES 1600000
#define HIDDEN  128
#define SCALING 0.25f

// ---------------- scratch (device globals) ----------------------------------
__device__ float g_q[(size_t)N_NODES * HIDDEN / 2 + 64];
__device__ float g_k[(size_t)N_NODES * HIDDEN / 2 + 64];
__device__ float g_v[(size_t)N_NODES * HIDDEN / 2 + 64];
__device__ float g_mid[(size_t)N_NODES * HIDDEN / 2 + 64];   // fp16
__device__ int   g_colsorted[N_EDGES];
#define CNT_TILE_OFF (N_NODES + 8)
#define CNT_CTR_OFF  (N_NODES + 8 + 256)
__device__ int   g_cnt[N_NODES + 8 + 256 + 8];
__device__ int   g_start[N_NODES + 1];
__device__ int   g_cursor[N_NODES];
__device__ int   g_is64;
// fp16 weight images: [n][k] ldmatrix-swizzled; hi 16384 ushorts + lo 16384.
__device__ unsigned short g_wimg[4][32768];
__device__ float g_biasP[4][128];

// swizzled byte offset of (row, k) in a [128 x 128] 16-bit tile
__device__ __forceinline__ int swz_off(int row, int k) {
    return row * 256 + ((((k >> 3) ^ (row & 7)) << 4)) + ((k & 7) << 1);
}
__device__ __forceinline__ uint32_t smem_to_u32(const void* p) {
    uint32_t a;
    asm("{ .reg .u64 t; cvta.to.shared.u64 t, %1; cvt.u32.u64 %0, t; }" : "=r"(a) : "l"(p));
    return a;
}
__device__ __forceinline__ void ldsm4(uint32_t addr, uint32_t r[4]) {
    asm volatile("ldmatrix.sync.aligned.m8n8.x4.shared.b16 {%0,%1,%2,%3}, [%4];"
        : "=r"(r[0]), "=r"(r[1]), "=r"(r[2]), "=r"(r[3]) : "r"(addr));
}
__device__ __forceinline__ void mma16816h(float c[4], const uint32_t a[4],
                                          uint32_t b0, uint32_t b1) {
    asm volatile("mma.sync.aligned.m16n8k16.row.col.f32.f16.f16.f32 "
        "{%0,%1,%2,%3}, {%4,%5,%6,%7}, {%8,%9}, {%0,%1,%2,%3};"
        : "+f"(c[0]), "+f"(c[1]), "+f"(c[2]), "+f"(c[3])
        : "r"(a[0]), "r"(a[1]), "r"(a[2]), "r"(a[3]), "r"(b0), "r"(b1));
}

// ---------------- hist (with built-in dtype detect) --------------------------
__global__ void k_hist(const void* rowp, int E) {
    __shared__ int s_is64;
    if (threadIdx.x == 0) s_is64 = 1;
    __syncthreads();
    if (threadIdx.x < 64) {
        long long v = ((const long long*)rowp)[threadIdx.x];
        if (v < 0 || v >= (1LL << 31)) atomicAnd(&s_is64, 0);
    }
    __syncthreads();
    int is64 = s_is64;
    if (blockIdx.x == 0 && threadIdx.x == 0) g_is64 = is64;
    int stride = gridDim.x * blockDim.x;
    for (int i = blockIdx.x * blockDim.x + threadIdx.x; i < E; i += stride) {
        int r = is64 ? (int)((const long long*)rowp)[i] : ((const int*)rowp)[i];
        atomicAdd(&g_cnt[r], 1);
    }
}

// ---------------- single-pass exclusive scan (decoupled lookback) ------------
__global__ void k_scan1(int n, int E) {
    __shared__ int sh[1024];
    __shared__ int s_bid, s_prev;
    unsigned* tile = (unsigned*)(g_cnt + CNT_TILE_OFF);
    const int tid = threadIdx.x;
    if (tid == 0) s_bid = atomicAdd(g_cnt + CNT_CTR_OFF, 1);
    __syncthreads();
    const int bid = s_bid;
    const int i = bid * 1024 + tid;
    int v = (i < n) ? g_cnt[i] : 0;
    sh[tid] = v;
    __syncthreads();
    for (int off = 1; off < 1024; off <<= 1) {
        int t = (tid >= off) ? sh[tid - off] : 0;
        __syncthreads();
        sh[tid] += t;
        __syncthreads();
    }
    int total = sh[1023];
    if (tid == 0) {
        unsigned flag = (bid == 0) ? 2u : 1u;
        atomicExch(&tile[bid], (flag << 30) | ((unsigned)total & 0x00FFFFFFu));
        if (bid == 0) s_prev = 0;
    }
    if (bid > 0 && tid < 32) {
        int lane = tid;
        int prev = 0;
        int look = bid - 1;
        while (true) {
            int idx = look - lane;
            unsigned st;
            do {
                st = (idx >= 0) ? atomicAdd(&tile[idx], 0u) : (2u << 30);
            } while (__any_sync(0xffffffffu, (st >> 30) == 0u));
            unsigned pmask = __ballot_sync(0xffffffffu, (st >> 30) >= 2u);
            int lim = pmask ? (__ffs(pmask) - 1) : 31;
            int val = (lane <= lim) ? (int)(st & 0x00FFFFFFu) : 0;
            #pragma unroll
            for (int o = 16; o; o >>= 1) val += __shfl_xor_sync(0xffffffffu, val, o);
            prev += val;
            if (pmask) break;
            look -= 32;
        }
        if (lane == 0) {
            s_prev = prev;
            atomicExch(&tile[bid], (2u << 30) | ((unsigned)(prev + total) & 0x00FFFFFFu));
        }
    }
    __syncthreads();
    int pre = s_prev;
    if (i < n) {
        int ex = pre + sh[tid] - v;
        g_start[i]  = ex;
        g_cursor[i] = ex;
    }
    if (i == n) g_start[n] = E;
}

// ---------------- standalone edge scatter -------------------------------------
__global__ void k_scat(const void* rowp, const void* colp, int E) {
    int is64 = g_is64;
    int stride = gridDim.x * blockDim.x;
    for (int i = blockIdx.x * blockDim.x + threadIdx.x; i < E; i += stride) {
        int r, cc;
        if (is64) {
            r  = (int)((const long long*)rowp)[i];
            cc = (int)((const long long*)colp)[i];
        } else {
            r  = ((const int*)rowp)[i];
            cc = ((const int*)colp)[i];
        }
        int pos = atomicAdd(&g_cursor[r], 1);
        g_colsorted[pos] = cc;
    }
}

// ---------------- weight conversion (once, tiny): all fp16 hi/lo -------------
__global__ void k_wconv(const float* Wq, const float* bq, const float* Wk, const float* bk,
                        const float* Wv, const float* bv, const float* Wo, const float* bo) {
    int g = blockIdx.x, tid = threadIdx.x;
    const float* W = g == 0 ? Wq : g == 1 ? Wk : g == 2 ? Wv : Wo;
    const float* b = g == 0 ? bq : g == 1 ? bk : g == 2 ? bv : bo;
    float scale = (g == 0) ? SCALING : 1.0f;
    char* hi = (char*)g_wimg[g];
    char* lo = (char*)(g_wimg[g] + 16384);
    for (int i = tid; i < 16384; i += 256) {
        int n = i >> 7, k = i & 127;
        int sr = (g < 3) ? ((n & 15) * 8 + (n >> 4)) : n;
        int sk = (g == 3) ? ((k & 15) * 8 + (k >> 4)) : k;
        float v = W[sr * 128 + sk] * scale;
        __half h = __float2half(v);
        __half l = __float2half(v - __half2float(h));
        int sw = swz_off(n, k);
        *(unsigned short*)(hi + sw) = __half_as_ushort(h);
        *(unsigned short*)(lo + sw) = __half_as_ushort(l);
    }
    if (tid < 128)
        g_biasP[g][tid] = b[(g < 3) ? ((tid & 15) * 8 + (tid >> 4)) : tid] * scale;
}

// ---------------- GEMM via mma.sync fp16 2-term (A exact-or-rounded fp16) ----
// Block tile 128x128; 8 warps = 4(M)x2(N); 67.5KB smem -> 2 CTAs/SM.
// A: INF16 ? already fp16 : fp32 rounded to fp16 (error ~2^-12, same class as
// the fp16 q/k/v rounding already accepted). B consumed in two 32KB phases
// (fp16 hi image then lo image); D = A*Bh + A*Bl. 256 mma/warp/stage.
#define SMEM_MMA (2048 + 32768 + 32768)
template<bool OUTF16, bool INF16>
__global__ void __launch_bounds__(256, 2)
k_mma(const void* __restrict__ Xv, int nrows, int wbase, int nst,
      void* __restrict__ o0, void* __restrict__ o1, void* __restrict__ o2) {
    extern __shared__ __align__(16) char smem[];
    float* sbias = (float*)smem;
    char*  As    = smem + 2048;
    char*  Bs    = smem + 2048 + 32768;
    uint32_t sbA = smem_to_u32(As);
    uint32_t sbB = smem_to_u32(Bs);

    const int tid = threadIdx.x;
    const int lane = tid & 31;
    const int wid = tid >> 5;
    const int warp_m = wid & 3;
    const int warp_n = wid >> 2;
    const int rowBase = blockIdx.x * 128;

    if (tid < 128)
        for (int s = 0; s < nst; s++) sbias[s * 128 + tid] = g_biasP[wbase + s][tid];

    if (INF16) {
        const char* X = (const char*)Xv;
        #pragma unroll
        for (int kk = 0; kk < 8; kk++) {
            int idx = tid + kk * 256;          // 2048 chunks of 16B
            int r = idx >> 4, ch = idx & 15;
            uint4 x = make_uint4(0, 0, 0, 0);
            if (rowBase + r < nrows)
                x = *(const uint4*)(X + (size_t)(rowBase + r) * 256 + ch * 16);
            *(uint4*)(As + r * 256 + ((ch ^ (r & 7)) << 4)) = x;
        }
    } else {
        const float* X = (const float*)Xv;
        #pragma unroll
        for (int kk = 0; kk < 16; kk++) {
            int idx = tid + kk * 256;
            int r = idx >> 5, m4 = (idx & 31) << 2;
            float4 x = make_float4(0.f, 0.f, 0.f, 0.f);
            if (rowBase + r < nrows)
                x = *(const float4*)(X + (size_t)(rowBase + r) * 128 + m4);
            __half2 p01 = __floats2half2_rn(x.x, x.y);
            __half2 p23 = __floats2half2_rn(x.z, x.w);
            uint2 u;
            u.x = *reinterpret_cast<uint32_t*>(&p01);
            u.y = *reinterpret_cast<uint32_t*>(&p23);
            *(uint2*)(As + swz_off(r, m4)) = u;
        }
    }

    const int rA  = warp_m * 32 + (lane & 15);
    const int aAdd = lane >> 4;
    const int rB  = warp_n * 64 + (lane & 7) + ((lane >> 4) << 3);
    const int bAdd = (lane >> 3) & 1;

    void* outs[3] = {o0, o1, o2};
    for (int s = 0; s < nst; s++) {
        float c[2][8][4];
        #pragma unroll
        for (int mf = 0; mf < 2; mf++)
            #pragma unroll
            for (int nf = 0; nf < 8; nf++)
                #pragma unroll
                for (int t = 0; t < 4; t++) c[mf][nf][t] = 0.f;

        #pragma unroll
        for (int ph = 0; ph < 2; ph++) {
            __syncthreads();
            {
                const uint4* src = (const uint4*)(g_wimg[wbase + s] + ph * 16384);
                #pragma unroll
                for (int kk = 0; kk < 8; kk++)
                    ((uint4*)Bs)[tid + kk * 256] = src[tid + kk * 256];
            }
            __syncthreads();
            #pragma unroll
            for (int ks = 0; ks < 8; ks++) {
                const int chA = 2 * ks + aAdd;
                const int chB = 2 * ks + bAdd;
                uint32_t Ah[2][4];
                #pragma unroll
                for (int mf = 0; mf < 2; mf++) {
                    int row = rA + mf * 16;
                    ldsm4(sbA + row * 256 + (((chA ^ (row & 7))) << 4), Ah[mf]);
                }
                #pragma unroll
                for (int nf16 = 0; nf16 < 4; nf16++) {
                    int row = rB + nf16 * 16;
                    uint32_t Bf[4];
                    ldsm4(sbB + row * 256 + (((chB ^ (row & 7))) << 4), Bf);
                    #pragma unroll
                    for (int mf = 0; mf < 2; mf++) {
                        mma16816h(c[mf][2 * nf16],     Ah[mf], Bf[0], Bf[1]);
                        mma16816h(c[mf][2 * nf16 + 1], Ah[mf], Bf[2], Bf[3]);
                    }
                }
            }
        }

        // epilogue
        #pragma unroll
        for (int mf = 0; mf < 2; mf++) {
            int m0 = rowBase + warp_m * 32 + mf * 16 + (lane >> 2);
            #pragma unroll
            for (int nf = 0; nf < 8; nf++) {
                int n = warp_n * 64 + nf * 8 + ((lane & 3) << 1);
                float b0 = sbias[s * 128 + n], b1 = sbias[s * 128 + n + 1];
                if (OUTF16) {
                    __half2* O = (__half2*)outs[s];
                    if (m0 < nrows)
                        O[(size_t)m0 * 64 + (n >> 1)] =
                            __floats2half2_rn(c[mf][nf][0] + b0, c[mf][nf][1] + b1);
                    if (m0 + 8 < nrows)
                        O[(size_t)(m0 + 8) * 64 + (n >> 1)] =
                            __floats2half2_rn(c[mf][nf][2] + b0, c[mf][nf][3] + b1);
                } else {
                    float* O = (float*)outs[s];
                    if (m0 < nrows)
                        *(float2*)(O + (size_t)m0 * 128 + n) =
                            make_float2(c[mf][nf][0] + b0, c[mf][nf][1] + b1);
                    if (m0 + 8 < nrows)
                        *(float2*)(O + (size_t)(m0 + 8) * 128 + n) =
                            make_float2(c[mf][nf][2] + b0, c[mf][nf][3] + b1);
                }
            }
        }
    }
}

// ---------------- per-row attention (one warp per destination node) ---------
// q/k/v fp16 HEAD-MAJOR; mid fp16. Simple batch-4 loop (best config).
__global__ void k_attn(int n) {
    int gw = (blockIdx.x * blockDim.x + threadIdx.x) >> 5;
    int lane = threadIdx.x & 31;
    if (gw >= n) return;
    int s0 = g_start[gw], s1 = g_start[gw + 1];
    const __half* qh = (const __half*)g_q;
    const __half* kh = (const __half*)g_k;
    const __half* vh = (const __half*)g_v;

    uint2 qr = *(const uint2*)(qh + (size_t)gw * 128 + lane * 4);
    float2 q01 = __half22float2(*reinterpret_cast<__half2*>(&qr.x));
    float2 q23 = __half22float2(*reinterpret_cast<__half2*>(&qr.y));

    float a0 = 0.f, a1 = 0.f, a2 = 0.f, a3 = 0.f, s = 0.f;

    int e = s0;
    for (; e + 4 <= s1; e += 4) {
        int c0 = g_colsorted[e + 0];
        int c1 = g_colsorted[e + 1];
        int c2 = g_colsorted[e + 2];
        int c3 = g_colsorted[e + 3];
        uint2 kr0 = *(const uint2*)(kh + (size_t)c0 * 128 + lane * 4);
        uint2 kr1 = *(const uint2*)(kh + (size_t)c1 * 128 + lane * 4);
        uint2 kr2 = *(const uint2*)(kh + (size_t)c2 * 128 + lane * 4);
        uint2 kr3 = *(const uint2*)(kh + (size_t)c3 * 128 + lane * 4);
        uint2 vr0 = *(const uint2*)(vh + (size_t)c0 * 128 + lane * 4);
        uint2 vr1 = *(const uint2*)(vh + (size_t)c1 * 128 + lane * 4);
        uint2 vr2 = *(const uint2*)(vh + (size_t)c2 * 128 + lane * 4);
        uint2 vr3 = *(const uint2*)(vh + (size_t)c3 * 128 + lane * 4);

        uint2 krs[4] = {kr0, kr1, kr2, kr3};
        uint2 vrs[4] = {vr0, vr1, vr2, vr3};
        float p[4];
        #pragma unroll
        for (int j = 0; j < 4; j++) {
            float2 k01 = __half22float2(*reinterpret_cast<__half2*>(&krs[j].x));
            float2 k23 = __half22float2(*reinterpret_cast<__half2*>(&krs[j].y));
            float t = q01.x * k01.x;
            t = fmaf(q01.y, k01.y, t);
            t = fmaf(q23.x, k23.x, t);
            t = fmaf(q23.y, k23.y, t);
            p[j] = t;
        }
        #pragma unroll
        for (int j = 0; j < 4; j++) p[j] += __shfl_xor_sync(0xffffffffu, p[j], 1);
        #pragma unroll
        for (int j = 0; j < 4; j++) p[j] += __shfl_xor_sync(0xffffffffu, p[j], 2);
        #pragma unroll
        for (int j = 0; j < 4; j++) {
            float ex = __expf(p[j]);
            float2 v01 = __half22float2(*reinterpret_cast<__half2*>(&vrs[j].x));
            float2 v23 = __half22float2(*reinterpret_cast<__half2*>(&vrs[j].y));
            s += ex;
            a0 = fmaf(ex, v01.x, a0);
            a1 = fmaf(ex, v01.y, a1);
            a2 = fmaf(ex, v23.x, a2);
            a3 = fmaf(ex, v23.y, a3);
        }
    }
    for (; e < s1; e++) {
        int c = g_colsorted[e];
        uint2 kr = *(const uint2*)(kh + (size_t)c * 128 + lane * 4);
        uint2 vr = *(const uint2*)(vh + (size_t)c * 128 + lane * 4);
        float2 k01 = __half22float2(*reinterpret_cast<__half2*>(&kr.x));
        float2 k23 = __half22float2(*reinterpret_cast<__half2*>(&kr.y));
        float2 v01 = __half22float2(*reinterpret_cast<__half2*>(&vr.x));
        float2 v23 = __half22float2(*reinterpret_cast<__half2*>(&vr.y));
        float p = q01.x * k01.x;
        p = fmaf(q01.y, k01.y, p);
        p = fmaf(q23.x, k23.x, p);
        p = fmaf(q23.y, k23.y, p);
        p += __shfl_xor_sync(0xffffffffu, p, 1);
        p += __shfl_xor_sync(0xffffffffu, p, 2);
        float ex = __expf(p);
        s += ex;
        a0 = fmaf(ex, v01.x, a0);
        a1 = fmaf(ex, v01.y, a1);
        a2 = fmaf(ex, v23.x, a2);
        a3 = fmaf(ex, v23.y, a3);
    }
    float inv = (s > 0.f) ? 1.f / s : 0.f;
    __half2* mh = (__half2*)g_mid;
    mh[(size_t)gw * 64 + lane * 2 + 0] = __floats2half2_rn(a0 * inv, a1 * inv);
    mh[(size_t)gw * 64 + lane * 2 + 1] = __floats2half2_rn(a2 * inv, a3 * inv);
}

// ---------------- launch ------------------------------------------------------
extern "C" void kernel_launch(void* const* d_in, const int* in_sizes, int n_in,
                              void* d_out, int out_size) {
    const float* h    = (const float*)d_in[0];
    const void*  rowp = d_in[1];
    const void*  colp = d_in[2];
    const float* Wq = (const float*)d_in[3];
    const float* bq = (const float*)d_in[4];
    const float* Wk = (const float*)d_in[5];
    const float* bk = (const float*)d_in[6];
    const float* Wv = (const float*)d_in[7];
    const float* bv = (const float*)d_in[8];
    const float* Wo = (const float*)d_in[9];
    const float* bo = (const float*)d_in[10];
    float* out = (float*)d_out;

    int N = in_sizes[0] / HIDDEN;
    int E = in_sizes[1];

    cudaFuncSetAttribute((const void*)k_mma<true, false>,
                         cudaFuncAttributeMaxDynamicSharedMemorySize, SMEM_MMA);
    cudaFuncSetAttribute((const void*)k_mma<false, true>,
                         cudaFuncAttributeMaxDynamicSharedMemorySize, SMEM_MMA);

    void *pq, *pk, *pv, *pmid, *pcnt;
    cudaGetSymbolAddress(&pq, g_q);
    cudaGetSymbolAddress(&pk, g_k);
    cudaGetSymbolAddress(&pv, g_v);
    cudaGetSymbolAddress(&pmid, g_mid);
    cudaGetSymbolAddress(&pcnt, g_cnt);

    int gb = (N + 127) / 128;
    int nb = (N + 1 + 1023) / 1024;

    // One-time side stream + fork/join events (cached; destroying them during
    // graph capture would invalidate the capture). No device allocations.
    static cudaStream_t side = nullptr;
    static cudaEvent_t evFork = nullptr, evJoin = nullptr;
    if (!side) {
        cudaStreamCreateWithFlags(&side, cudaStreamNonBlocking);
        cudaEventCreateWithFlags(&evFork, cudaEventDisableTiming);
        cudaEventCreateWithFlags(&evJoin, cudaEventDisableTiming);
    }

    // main: memset -> (fork) wconv -> qkv -> (join) -> attn -> gemm_o
    // side:          hist -> scan -> scat
    cudaMemsetAsync(pcnt, 0, sizeof(g_cnt));
    cudaEventRecord(evFork, 0);
    cudaStreamWaitEvent(side, evFork, 0);
    k_hist<<<1024, 256, 0, side>>>(rowp, E);
    k_scan1<<<nb, 1024, 0, side>>>(N, E);
    k_scat<<<1024, 256, 0, side>>>(rowp, colp, E);
    cudaEventRecord(evJoin, side);

    k_wconv<<<4, 256>>>(Wq, bq, Wk, bk, Wv, bv, Wo, bo);
    k_mma<true, false><<<gb, 256, SMEM_MMA>>>(h, N, 0, 3, pq, pk, pv);

    cudaStreamWaitEvent(0, evJoin, 0);
    k_attn<<<(N + 7) / 8, 256>>>(N);
    k_mma<false, true><<<gb, 256, SMEM_MMA>>>(pmid, N, 3, 1, out, 0, 0);
}

// round 16
// speedup vs baseline: 1.4806x; 1.1006x over previous
#include <cuda_runtime.h>
#include <cuda_fp16.h>
#include <math.h>
#include <cstdint>

#define N_NODES 100000
#define N_EDGES 1600000
#define HIDDEN  128
#define SCALING 0.25f

// ---------------- scratch (device globals) ----------------------------------
__device__ float g_q[(size_t)N_NODES * HIDDEN / 2 + 64];
__device__ float g_k[(size_t)N_NODES * HIDDEN / 2 + 64];
__device__ float g_v[(size_t)N_NODES * HIDDEN / 2 + 64];
__device__ float g_mid[(size_t)N_NODES * HIDDEN / 2 + 64];   // fp16
__device__ int   g_colsorted[N_EDGES];
#define CNT_TILE_OFF (N_NODES + 8)
#define CNT_CTR_OFF  (N_NODES + 8 + 256)
__device__ int   g_cnt[N_NODES + 8 + 256 + 8];
__device__ int   g_start[N_NODES + 1];
__device__ int   g_cursor[N_NODES];
__device__ int   g_is64;
// fp16 weight images: [n][k] ldmatrix-swizzled; hi 16384 ushorts + lo 16384.
__device__ unsigned short g_wimg[4][32768];
__device__ float g_biasP[4][128];

// swizzled byte offset of (row, k) in a [128 x 128] 16-bit tile
__device__ __forceinline__ int swz_off(int row, int k) {
    return row * 256 + ((((k >> 3) ^ (row & 7)) << 4)) + ((k & 7) << 1);
}
__device__ __forceinline__ uint32_t smem_to_u32(const void* p) {
    uint32_t a;
    asm("{ .reg .u64 t; cvta.to.shared.u64 t, %1; cvt.u32.u64 %0, t; }" : "=r"(a) : "l"(p));
    return a;
}
__device__ __forceinline__ void ldsm4(uint32_t addr, uint32_t r[4]) {
    asm volatile("ldmatrix.sync.aligned.m8n8.x4.shared.b16 {%0,%1,%2,%3}, [%4];"
        : "=r"(r[0]), "=r"(r[1]), "=r"(r[2]), "=r"(r[3]) : "r"(addr));
}
__device__ __forceinline__ void mma16816h(float c[4], const uint32_t a[4],
                                          uint32_t b0, uint32_t b1) {
    asm volatile("mma.sync.aligned.m16n8k16.row.col.f32.f16.f16.f32 "
        "{%0,%1,%2,%3}, {%4,%5,%6,%7}, {%8,%9}, {%0,%1,%2,%3};"
        : "+f"(c[0]), "+f"(c[1]), "+f"(c[2]), "+f"(c[3])
        : "r"(a[0]), "r"(a[1]), "r"(a[2]), "r"(a[3]), "r"(b0), "r"(b1));
}

// ---------------- hist (with built-in dtype detect) --------------------------
__global__ void k_hist(const void* rowp, int E) {
    __shared__ int s_is64;
    if (threadIdx.x == 0) s_is64 = 1;
    __syncthreads();
    if (threadIdx.x < 64) {
        long long v = ((const long long*)rowp)[threadIdx.x];
        if (v < 0 || v >= (1LL << 31)) atomicAnd(&s_is64, 0);
    }
    __syncthreads();
    int is64 = s_is64;
    if (blockIdx.x == 0 && threadIdx.x == 0) g_is64 = is64;
    int stride = gridDim.x * blockDim.x;
    for (int i = blockIdx.x * blockDim.x + threadIdx.x; i < E; i += stride) {
        int r = is64 ? (int)((const long long*)rowp)[i] : ((const int*)rowp)[i];
        atomicAdd(&g_cnt[r], 1);
    }
}

// ---------------- single-pass exclusive scan (decoupled lookback) ------------
__global__ void k_scan1(int n, int E) {
    __shared__ int sh[1024];
    __shared__ int s_bid, s_prev;
    unsigned* tile = (unsigned*)(g_cnt + CNT_TILE_OFF);
    const int tid = threadIdx.x;
    if (tid == 0) s_bid = atomicAdd(g_cnt + CNT_CTR_OFF, 1);
    __syncthreads();
    const int bid = s_bid;
    const int i = bid * 1024 + tid;
    int v = (i < n) ? g_cnt[i] : 0;
    sh[tid] = v;
    __syncthreads();
    for (int off = 1; off < 1024; off <<= 1) {
        int t = (tid >= off) ? sh[tid - off] : 0;
        __syncthreads();
        sh[tid] += t;
        __syncthreads();
    }
    int total = sh[1023];
    if (tid == 0) {
        unsigned flag = (bid == 0) ? 2u : 1u;
        atomicExch(&tile[bid], (flag << 30) | ((unsigned)total & 0x00FFFFFFu));
        if (bid == 0) s_prev = 0;
    }
    if (bid > 0 && tid < 32) {
        int lane = tid;
        int prev = 0;
        int look = bid - 1;
        while (true) {
            int idx = look - lane;
            unsigned st;
            do {
                st = (idx >= 0) ? atomicAdd(&tile[idx], 0u) : (2u << 30);
            } while (__any_sync(0xffffffffu, (st >> 30) == 0u));
            unsigned pmask = __ballot_sync(0xffffffffu, (st >> 30) >= 2u);
            int lim = pmask ? (__ffs(pmask) - 1) : 31;
            int val = (lane <= lim) ? (int)(st & 0x00FFFFFFu) : 0;
            #pragma unroll
            for (int o = 16; o; o >>= 1) val += __shfl_xor_sync(0xffffffffu, val, o);
            prev += val;
            if (pmask) break;
            look -= 32;
        }
        if (lane == 0) {
            s_prev = prev;
            atomicExch(&tile[bid], (2u << 30) | ((unsigned)(prev + total) & 0x00FFFFFFu));
        }
    }
    __syncthreads();
    int pre = s_prev;
    if (i < n) {
        int ex = pre + sh[tid] - v;
        g_start[i]  = ex;
        g_cursor[i] = ex;
    }
    if (i == n) g_start[n] = E;
}

// ---------------- standalone edge scatter -------------------------------------
__global__ void k_scat(const void* rowp, const void* colp, int E) {
    int is64 = g_is64;
    int stride = gridDim.x * blockDim.x;
    for (int i = blockIdx.x * blockDim.x + threadIdx.x; i < E; i += stride) {
        int r, cc;
        if (is64) {
            r  = (int)((const long long*)rowp)[i];
            cc = (int)((const long long*)colp)[i];
        } else {
            r  = ((const int*)rowp)[i];
            cc = ((const int*)colp)[i];
        }
        int pos = atomicAdd(&g_cursor[r], 1);
        g_colsorted[pos] = cc;
    }
}

// ---------------- weight conversion: fp16 hi/lo, 128 blocks ------------------
// 32 blocks per matrix, 512 elements each (2 iters/thread) — latency spread
// across SMs instead of 4 serialized blocks (was 32.7us at occ 12%).
__global__ void k_wconv(const float* Wq, const float* bq, const float* Wk, const float* bk,
                        const float* Wv, const float* bv, const float* Wo, const float* bo) {
    int g   = blockIdx.x >> 5;      // 0..3
    int sub = blockIdx.x & 31;      // 0..31
    int tid = threadIdx.x;
    const float* W = g == 0 ? Wq : g == 1 ? Wk : g == 2 ? Wv : Wo;
    const float* b = g == 0 ? bq : g == 1 ? bk : g == 2 ? bv : bo;
    float scale = (g == 0) ? SCALING : 1.0f;
    char* hi = (char*)g_wimg[g];
    char* lo = (char*)(g_wimg[g] + 16384);
    int base = sub * 512;
    #pragma unroll
    for (int it = 0; it < 2; it++) {
        int i = base + it * 256 + tid;
        int n = i >> 7, k = i & 127;
        int sr = (g < 3) ? ((n & 15) * 8 + (n >> 4)) : n;
        int sk = (g == 3) ? ((k & 15) * 8 + (k >> 4)) : k;
        float v = W[sr * 128 + sk] * scale;
        __half h = __float2half(v);
        __half l = __float2half(v - __half2float(h));
        int sw = swz_off(n, k);
        *(unsigned short*)(hi + sw) = __half_as_ushort(h);
        *(unsigned short*)(lo + sw) = __half_as_ushort(l);
    }
    if (sub == 0 && tid < 128)
        g_biasP[g][tid] = b[(g < 3) ? ((tid & 15) * 8 + (tid >> 4)) : tid] * scale;
}

// ---------------- GEMM via mma.sync fp16 2-term ------------------------------
// Block tile 128x128; 8 warps = 4(M)x2(N); 67.5KB smem -> 2 CTAs/SM.
// A: INF16 ? already fp16 : fp32 rounded to fp16. B consumed in two 32KB
// phases (fp16 hi image then lo image); D = A*Bh + A*Bl. 256 mma/warp/stage.
#define SMEM_MMA (2048 + 32768 + 32768)
template<bool OUTF16, bool INF16>
__global__ void __launch_bounds__(256, 2)
k_mma(const void* __restrict__ Xv, int nrows, int wbase, int nst,
      void* __restrict__ o0, void* __restrict__ o1, void* __restrict__ o2) {
    extern __shared__ __align__(16) char smem[];
    float* sbias = (float*)smem;
    char*  As    = smem + 2048;
    char*  Bs    = smem + 2048 + 32768;
    uint32_t sbA = smem_to_u32(As);
    uint32_t sbB = smem_to_u32(Bs);

    const int tid = threadIdx.x;
    const int lane = tid & 31;
    const int wid = tid >> 5;
    const int warp_m = wid & 3;
    const int warp_n = wid >> 2;
    const int rowBase = blockIdx.x * 128;

    if (tid < 128)
        for (int s = 0; s < nst; s++) sbias[s * 128 + tid] = g_biasP[wbase + s][tid];

    if (INF16) {
        const char* X = (const char*)Xv;
        #pragma unroll
        for (int kk = 0; kk < 8; kk++) {
            int idx = tid + kk * 256;
            int r = idx >> 4, ch = idx & 15;
            uint4 x = make_uint4(0, 0, 0, 0);
            if (rowBase + r < nrows)
                x = *(const uint4*)(X + (size_t)(rowBase + r) * 256 + ch * 16);
            *(uint4*)(As + r * 256 + ((ch ^ (r & 7)) << 4)) = x;
        }
    } else {
        const float* X = (const float*)Xv;
        #pragma unroll
        for (int kk = 0; kk < 16; kk++) {
            int idx = tid + kk * 256;
            int r = idx >> 5, m4 = (idx & 31) << 2;
            float4 x = make_float4(0.f, 0.f, 0.f, 0.f);
            if (rowBase + r < nrows)
                x = *(const float4*)(X + (size_t)(rowBase + r) * 128 + m4);
            __half2 p01 = __floats2half2_rn(x.x, x.y);
            __half2 p23 = __floats2half2_rn(x.z, x.w);
            uint2 u;
            u.x = *reinterpret_cast<uint32_t*>(&p01);
            u.y = *reinterpret_cast<uint32_t*>(&p23);
            *(uint2*)(As + swz_off(r, m4)) = u;
        }
    }

    const int rA  = warp_m * 32 + (lane & 15);
    const int aAdd = lane >> 4;
    const int rB  = warp_n * 64 + (lane & 7) + ((lane >> 4) << 3);
    const int bAdd = (lane >> 3) & 1;

    void* outs[3] = {o0, o1, o2};
    for (int s = 0; s < nst; s++) {
        float c[2][8][4];
        #pragma unroll
        for (int mf = 0; mf < 2; mf++)
            #pragma unroll
            for (int nf = 0; nf < 8; nf++)
                #pragma unroll
                for (int t = 0; t < 4; t++) c[mf][nf][t] = 0.f;

        #pragma unroll
        for (int ph = 0; ph < 2; ph++) {
            __syncthreads();
            {
                const uint4* src = (const uint4*)(g_wimg[wbase + s] + ph * 16384);
                #pragma unroll
                for (int kk = 0; kk < 8; kk++)
                    ((uint4*)Bs)[tid + kk * 256] = src[tid + kk * 256];
            }
            __syncthreads();
            #pragma unroll
            for (int ks = 0; ks < 8; ks++) {
                const int chA = 2 * ks + aAdd;
                const int chB = 2 * ks + bAdd;
                uint32_t Ah[2][4];
                #pragma unroll
                for (int mf = 0; mf < 2; mf++) {
                    int row = rA + mf * 16;
                    ldsm4(sbA + row * 256 + (((chA ^ (row & 7))) << 4), Ah[mf]);
                }
                #pragma unroll
                for (int nf16 = 0; nf16 < 4; nf16++) {
                    int row = rB + nf16 * 16;
                    uint32_t Bf[4];
                    ldsm4(sbB + row * 256 + (((chB ^ (row & 7))) << 4), Bf);
                    #pragma unroll
                    for (int mf = 0; mf < 2; mf++) {
                        mma16816h(c[mf][2 * nf16],     Ah[mf], Bf[0], Bf[1]);
                        mma16816h(c[mf][2 * nf16 + 1], Ah[mf], Bf[2], Bf[3]);
                    }
                }
            }
        }

        // epilogue
        #pragma unroll
        for (int mf = 0; mf < 2; mf++) {
            int m0 = rowBase + warp_m * 32 + mf * 16 + (lane >> 2);
            #pragma unroll
            for (int nf = 0; nf < 8; nf++) {
                int n = warp_n * 64 + nf * 8 + ((lane & 3) << 1);
                float b0 = sbias[s * 128 + n], b1 = sbias[s * 128 + n + 1];
                if (OUTF16) {
                    __half2* O = (__half2*)outs[s];
                    if (m0 < nrows)
                        O[(size_t)m0 * 64 + (n >> 1)] =
                            __floats2half2_rn(c[mf][nf][0] + b0, c[mf][nf][1] + b1);
                    if (m0 + 8 < nrows)
                        O[(size_t)(m0 + 8) * 64 + (n >> 1)] =
                            __floats2half2_rn(c[mf][nf][2] + b0, c[mf][nf][3] + b1);
                } else {
                    float* O = (float*)outs[s];
                    if (m0 < nrows)
                        *(float2*)(O + (size_t)m0 * 128 + n) =
                            make_float2(c[mf][nf][0] + b0, c[mf][nf][1] + b1);
                    if (m0 + 8 < nrows)
                        *(float2*)(O + (size_t)(m0 + 8) * 128 + n) =
                            make_float2(c[mf][nf][2] + b0, c[mf][nf][3] + b1);
                }
            }
        }
    }
}

// ---------------- per-row attention (one warp per destination node) ---------
// q/k/v fp16 HEAD-MAJOR; mid fp16. Simple batch-4 loop (best config).
__global__ void k_attn(int n) {
    int gw = (blockIdx.x * blockDim.x + threadIdx.x) >> 5;
    int lane = threadIdx.x & 31;
    if (gw >= n) return;
    int s0 = g_start[gw], s1 = g_start[gw + 1];
    const __half* qh = (const __half*)g_q;
    const __half* kh = (const __half*)g_k;
    const __half* vh = (const __half*)g_v;

    uint2 qr = *(const uint2*)(qh + (size_t)gw * 128 + lane * 4);
    float2 q01 = __half22float2(*reinterpret_cast<__half2*>(&qr.x));
    float2 q23 = __half22float2(*reinterpret_cast<__half2*>(&qr.y));

    float a0 = 0.f, a1 = 0.f, a2 = 0.f, a3 = 0.f, s = 0.f;

    int e = s0;
    for (; e + 4 <= s1; e += 4) {
        int c0 = g_colsorted[e + 0];
        int c1 = g_colsorted[e + 1];
        int c2 = g_colsorted[e + 2];
        int c3 = g_colsorted[e + 3];
        uint2 kr0 = *(const uint2*)(kh + (size_t)c0 * 128 + lane * 4);
        uint2 kr1 = *(const uint2*)(kh + (size_t)c1 * 128 + lane * 4);
        uint2 kr2 = *(const uint2*)(kh + (size_t)c2 * 128 + lane * 4);
        uint2 kr3 = *(const uint2*)(kh + (size_t)c3 * 128 + lane * 4);
        uint2 vr0 = *(const uint2*)(vh + (size_t)c0 * 128 + lane * 4);
        uint2 vr1 = *(const uint2*)(vh + (size_t)c1 * 128 + lane * 4);
        uint2 vr2 = *(const uint2*)(vh + (size_t)c2 * 128 + lane * 4);
        uint2 vr3 = *(const uint2*)(vh + (size_t)c3 * 128 + lane * 4);

        uint2 krs[4] = {kr0, kr1, kr2, kr3};
        uint2 vrs[4] = {vr0, vr1, vr2, vr3};
        float p[4];
        #pragma unroll
        for (int j = 0; j < 4; j++) {
            float2 k01 = __half22float2(*reinterpret_cast<__half2*>(&krs[j].x));
            float2 k23 = __half22float2(*reinterpret_cast<__half2*>(&krs[j].y));
            float t = q01.x * k01.x;
            t = fmaf(q01.y, k01.y, t);
            t = fmaf(q23.x, k23.x, t);
            t = fmaf(q23.y, k23.y, t);
            p[j] = t;
        }
        #pragma unroll
        for (int j = 0; j < 4; j++) p[j] += __shfl_xor_sync(0xffffffffu, p[j], 1);
        #pragma unroll
        for (int j = 0; j < 4; j++) p[j] += __shfl_xor_sync(0xffffffffu, p[j], 2);
        #pragma unroll
        for (int j = 0; j < 4; j++) {
            float ex = __expf(p[j]);
            float2 v01 = __half22float2(*reinterpret_cast<__half2*>(&vrs[j].x));
            float2 v23 = __half22float2(*reinterpret_cast<__half2*>(&vrs[j].y));
            s += ex;
            a0 = fmaf(ex, v01.x, a0);
            a1 = fmaf(ex, v01.y, a1);
            a2 = fmaf(ex, v23.x, a2);
            a3 = fmaf(ex, v23.y, a3);
        }
    }
    for (; e < s1; e++) {
        int c = g_colsorted[e];
        uint2 kr = *(const uint2*)(kh + (size_t)c * 128 + lane * 4);
        uint2 vr = *(const uint2*)(vh + (size_t)c * 128 + lane * 4);
        float2 k01 = __half22float2(*reinterpret_cast<__half2*>(&kr.x));
        float2 k23 = __half22float2(*reinterpret_cast<__half2*>(&kr.y));
        float2 v01 = __half22float2(*reinterpret_cast<__half2*>(&vr.x));
        float2 v23 = __half22float2(*reinterpret_cast<__half2*>(&vr.y));
        float p = q01.x * k01.x;
        p = fmaf(q01.y, k01.y, p);
        p = fmaf(q23.x, k23.x, p);
        p = fmaf(q23.y, k23.y, p);
        p += __shfl_xor_sync(0xffffffffu, p, 1);
        p += __shfl_xor_sync(0xffffffffu, p, 2);
        float ex = __expf(p);
        s += ex;
        a0 = fmaf(ex, v01.x, a0);
        a1 = fmaf(ex, v01.y, a1);
        a2 = fmaf(ex, v23.x, a2);
        a3 = fmaf(ex, v23.y, a3);
    }
    float inv = (s > 0.f) ? 1.f / s : 0.f;
    __half2* mh = (__half2*)g_mid;
    mh[(size_t)gw * 64 + lane * 2 + 0] = __floats2half2_rn(a0 * inv, a1 * inv);
    mh[(size_t)gw * 64 + lane * 2 + 1] = __floats2half2_rn(a2 * inv, a3 * inv);
}

// ---------------- launch ------------------------------------------------------
extern "C" void kernel_launch(void* const* d_in, const int* in_sizes, int n_in,
                              void* d_out, int out_size) {
    const float* h    = (const float*)d_in[0];
    const void*  rowp = d_in[1];
    const void*  colp = d_in[2];
    const float* Wq = (const float*)d_in[3];
    const float* bq = (const float*)d_in[4];
    const float* Wk = (const float*)d_in[5];
    const float* bk = (const float*)d_in[6];
    const float* Wv = (const float*)d_in[7];
    const float* bv = (const float*)d_in[8];
    const float* Wo = (const float*)d_in[9];
    const float* bo = (const float*)d_in[10];
    float* out = (float*)d_out;

    int N = in_sizes[0] / HIDDEN;
    int E = in_sizes[1];

    cudaFuncSetAttribute((const void*)k_mma<true, false>,
                         cudaFuncAttributeMaxDynamicSharedMemorySize, SMEM_MMA);
    cudaFuncSetAttribute((const void*)k_mma<false, true>,
                         cudaFuncAttributeMaxDynamicSharedMemorySize, SMEM_MMA);

    void *pq, *pk, *pv, *pmid, *pcnt;
    cudaGetSymbolAddress(&pq, g_q);
    cudaGetSymbolAddress(&pk, g_k);
    cudaGetSymbolAddress(&pv, g_v);
    cudaGetSymbolAddress(&pmid, g_mid);
    cudaGetSymbolAddress(&pcnt, g_cnt);

    int gb = (N + 127) / 128;
    int nb = (N + 1 + 1023) / 1024;

    // One-time side stream + fork/join events (cached across capture).
    static cudaStream_t side = nullptr;
    static cudaEvent_t evFork = nullptr, evJoin = nullptr;
    if (!side) {
        cudaStreamCreateWithFlags(&side, cudaStreamNonBlocking);
        cudaEventCreateWithFlags(&evFork, cudaEventDisableTiming);
        cudaEventCreateWithFlags(&evJoin, cudaEventDisableTiming);
    }

    // main: memset -> (fork) wconv -> qkv -> (join) -> attn -> gemm_o
    // side:          hist -> scan -> scat
    cudaMemsetAsync(pcnt, 0, sizeof(g_cnt));
    cudaEventRecord(evFork, 0);
    cudaStreamWaitEvent(side, evFork, 0);
    k_hist<<<1024, 256, 0, side>>>(rowp, E);
    k_scan1<<<nb, 1024, 0, side>>>(N, E);
    k_scat<<<1024, 256, 0, side>>>(rowp, colp, E);
    cudaEventRecord(evJoin, side);

    k_wconv<<<128, 256>>>(Wq, bq, Wk, bk, Wv, bv, Wo, bo);
    k_mma<true, false><<<gb, 256, SMEM_MMA>>>(h, N, 0, 3, pq, pk, pv);

    cudaStreamWaitEvent(0, evJoin, 0);
    k_attn<<<(N + 7) / 8, 256>>>(N);
    k_mma<false, true><<<gb, 256, SMEM_MMA>>>(pmid, N, 3, 1, out, 0, 0);
}

// round 17
// speedup vs baseline: 1.6926x; 1.1432x over previous
#include <cuda_runtime.h>
#include <cuda_fp16.h>
#include <math.h>
#include <cstdint>

#define N_NODES 100000
#define N_EDGES 1600000
#define HIDDEN  128
#define SCALING 0.25f

// ---------------- scratch (device globals) ----------------------------------
__device__ float g_q[(size_t)N_NODES * HIDDEN / 2 + 64];
__device__ float g_k[(size_t)N_NODES * HIDDEN / 2 + 64];
__device__ float g_v[(size_t)N_NODES * HIDDEN / 2 + 64];
__device__ float g_mid[(size_t)N_NODES * HIDDEN / 2 + 64];   // fp16
__device__ int   g_colsorted[N_EDGES];
#define CNT_TILE_OFF (N_NODES + 8)
#define CNT_CTR_OFF  (N_NODES + 8 + 256)
__device__ int   g_cnt[N_NODES + 8 + 256 + 8];
__device__ int   g_start[N_NODES + 1];
__device__ int   g_cursor[N_NODES];
__device__ int   g_is64;
// fp16 weight images: [n][k] ldmatrix-swizzled, single fp16 (no lo term).
__device__ unsigned short g_wimg[4][16384];
__device__ float g_biasP[4][128];

// swizzled byte offset of (row, k) in a [128 x 128] 16-bit tile
__device__ __forceinline__ int swz_off(int row, int k) {
    return row * 256 + ((((k >> 3) ^ (row & 7)) << 4)) + ((k & 7) << 1);
}
__device__ __forceinline__ uint32_t smem_to_u32(const void* p) {
    uint32_t a;
    asm("{ .reg .u64 t; cvta.to.shared.u64 t, %1; cvt.u32.u64 %0, t; }" : "=r"(a) : "l"(p));
    return a;
}
__device__ __forceinline__ void ldsm4(uint32_t addr, uint32_t r[4]) {
    asm volatile("ldmatrix.sync.aligned.m8n8.x4.shared.b16 {%0,%1,%2,%3}, [%4];"
        : "=r"(r[0]), "=r"(r[1]), "=r"(r[2]), "=r"(r[3]) : "r"(addr));
}
__device__ __forceinline__ void mma16816h(float c[4], const uint32_t a[4],
                                          uint32_t b0, uint32_t b1) {
    asm volatile("mma.sync.aligned.m16n8k16.row.col.f32.f16.f16.f32 "
        "{%0,%1,%2,%3}, {%4,%5,%6,%7}, {%8,%9}, {%0,%1,%2,%3};"
        : "+f"(c[0]), "+f"(c[1]), "+f"(c[2]), "+f"(c[3])
        : "r"(a[0]), "r"(a[1]), "r"(a[2]), "r"(a[3]), "r"(b0), "r"(b1));
}

// ---------------- hist (with built-in dtype detect) --------------------------
__global__ void k_hist(const void* rowp, int E) {
    __shared__ int s_is64;
    if (threadIdx.x == 0) s_is64 = 1;
    __syncthreads();
    if (threadIdx.x < 64) {
        long long v = ((const long long*)rowp)[threadIdx.x];
        if (v < 0 || v >= (1LL << 31)) atomicAnd(&s_is64, 0);
    }
    __syncthreads();
    int is64 = s_is64;
    if (blockIdx.x == 0 && threadIdx.x == 0) g_is64 = is64;
    int stride = gridDim.x * blockDim.x;
    for (int i = blockIdx.x * blockDim.x + threadIdx.x; i < E; i += stride) {
        int r = is64 ? (int)((const long long*)rowp)[i] : ((const int*)rowp)[i];
        atomicAdd(&g_cnt[r], 1);
    }
}

// ---------------- single-pass exclusive scan (decoupled lookback) ------------
__global__ void k_scan1(int n, int E) {
    __shared__ int sh[1024];
    __shared__ int s_bid, s_prev;
    unsigned* tile = (unsigned*)(g_cnt + CNT_TILE_OFF);
    const int tid = threadIdx.x;
    if (tid == 0) s_bid = atomicAdd(g_cnt + CNT_CTR_OFF, 1);
    __syncthreads();
    const int bid = s_bid;
    const int i = bid * 1024 + tid;
    int v = (i < n) ? g_cnt[i] : 0;
    sh[tid] = v;
    __syncthreads();
    for (int off = 1; off < 1024; off <<= 1) {
        int t = (tid >= off) ? sh[tid - off] : 0;
        __syncthreads();
        sh[tid] += t;
        __syncthreads();
    }
    int total = sh[1023];
    if (tid == 0) {
        unsigned flag = (bid == 0) ? 2u : 1u;
        atomicExch(&tile[bid], (flag << 30) | ((unsigned)total & 0x00FFFFFFu));
        if (bid == 0) s_prev = 0;
    }
    if (bid > 0 && tid < 32) {
        int lane = tid;
        int prev = 0;
        int look = bid - 1;
        while (true) {
            int idx = look - lane;
            unsigned st;
            do {
                st = (idx >= 0) ? atomicAdd(&tile[idx], 0u) : (2u << 30);
            } while (__any_sync(0xffffffffu, (st >> 30) == 0u));
            unsigned pmask = __ballot_sync(0xffffffffu, (st >> 30) >= 2u);
            int lim = pmask ? (__ffs(pmask) - 1) : 31;
            int val = (lane <= lim) ? (int)(st & 0x00FFFFFFu) : 0;
            #pragma unroll
            for (int o = 16; o; o >>= 1) val += __shfl_xor_sync(0xffffffffu, val, o);
            prev += val;
            if (pmask) break;
            look -= 32;
        }
        if (lane == 0) {
            s_prev = prev;
            atomicExch(&tile[bid], (2u << 30) | ((unsigned)(prev + total) & 0x00FFFFFFu));
        }
    }
    __syncthreads();
    int pre = s_prev;
    if (i < n) {
        int ex = pre + sh[tid] - v;
        g_start[i]  = ex;
        g_cursor[i] = ex;
    }
    if (i == n) g_start[n] = E;
}

// ---------------- standalone edge scatter -------------------------------------
__global__ void k_scat(const void* rowp, const void* colp, int E) {
    int is64 = g_is64;
    int stride = gridDim.x * blockDim.x;
    for (int i = blockIdx.x * blockDim.x + threadIdx.x; i < E; i += stride) {
        int r, cc;
        if (is64) {
            r  = (int)((const long long*)rowp)[i];
            cc = (int)((const long long*)colp)[i];
        } else {
            r  = ((const int*)rowp)[i];
            cc = ((const int*)colp)[i];
        }
        int pos = atomicAdd(&g_cursor[r], 1);
        g_colsorted[pos] = cc;
    }
}

// ---------------- weight conversion: single fp16, 128 blocks -----------------
__global__ void k_wconv(const float* Wq, const float* bq, const float* Wk, const float* bk,
                        const float* Wv, const float* bv, const float* Wo, const float* bo) {
    int g   = blockIdx.x >> 5;      // 0..3
    int sub = blockIdx.x & 31;      // 0..31
    int tid = threadIdx.x;
    const float* W = g == 0 ? Wq : g == 1 ? Wk : g == 2 ? Wv : Wo;
    const float* b = g == 0 ? bq : g == 1 ? bk : g == 2 ? bv : bo;
    float scale = (g == 0) ? SCALING : 1.0f;
    char* hi = (char*)g_wimg[g];
    int base = sub * 512;
    #pragma unroll
    for (int it = 0; it < 2; it++) {
        int i = base + it * 256 + tid;
        int n = i >> 7, k = i & 127;
        int sr = (g < 3) ? ((n & 15) * 8 + (n >> 4)) : n;
        int sk = (g == 3) ? ((k & 15) * 8 + (k >> 4)) : k;
        float v = W[sr * 128 + sk] * scale;
        *(unsigned short*)(hi + swz_off(n, k)) = __half_as_ushort(__float2half(v));
    }
    if (sub == 0 && tid < 128)
        g_biasP[g][tid] = b[(g < 3) ? ((tid & 15) * 8 + (tid >> 4)) : tid] * scale;
}

// ---------------- GEMM via mma.sync fp16 single-term -------------------------
// Block tile 128x128; 8 warps = 4(M)x2(N); 67.5KB smem -> 2 CTAs/SM.
// A: INF16 ? already fp16 : fp32 rounded to fp16. B: single fp16 image.
// D = A*B, 128 mma/warp/stage (single pass).
#define SMEM_MMA (2048 + 32768 + 32768)
template<bool OUTF16, bool INF16>
__global__ void __launch_bounds__(256, 2)
k_mma(const void* __restrict__ Xv, int nrows, int wbase, int nst,
      void* __restrict__ o0, void* __restrict__ o1, void* __restrict__ o2) {
    extern __shared__ __align__(16) char smem[];
    float* sbias = (float*)smem;
    char*  As    = smem + 2048;
    char*  Bs    = smem + 2048 + 32768;
    uint32_t sbA = smem_to_u32(As);
    uint32_t sbB = smem_to_u32(Bs);

    const int tid = threadIdx.x;
    const int lane = tid & 31;
    const int wid = tid >> 5;
    const int warp_m = wid & 3;
    const int warp_n = wid >> 2;
    const int rowBase = blockIdx.x * 128;

    if (tid < 128)
        for (int s = 0; s < nst; s++) sbias[s * 128 + tid] = g_biasP[wbase + s][tid];

    if (INF16) {
        const char* X = (const char*)Xv;
        #pragma unroll
        for (int kk = 0; kk < 8; kk++) {
            int idx = tid + kk * 256;
            int r = idx >> 4, ch = idx & 15;
            uint4 x = make_uint4(0, 0, 0, 0);
            if (rowBase + r < nrows)
                x = *(const uint4*)(X + (size_t)(rowBase + r) * 256 + ch * 16);
            *(uint4*)(As + r * 256 + ((ch ^ (r & 7)) << 4)) = x;
        }
    } else {
        const float* X = (const float*)Xv;
        #pragma unroll
        for (int kk = 0; kk < 16; kk++) {
            int idx = tid + kk * 256;
            int r = idx >> 5, m4 = (idx & 31) << 2;
            float4 x = make_float4(0.f, 0.f, 0.f, 0.f);
            if (rowBase + r < nrows)
                x = *(const float4*)(X + (size_t)(rowBase + r) * 128 + m4);
            __half2 p01 = __floats2half2_rn(x.x, x.y);
            __half2 p23 = __floats2half2_rn(x.z, x.w);
            uint2 u;
            u.x = *reinterpret_cast<uint32_t*>(&p01);
            u.y = *reinterpret_cast<uint32_t*>(&p23);
            *(uint2*)(As + swz_off(r, m4)) = u;
        }
    }

    const int rA  = warp_m * 32 + (lane & 15);
    const int aAdd = lane >> 4;
    const int rB  = warp_n * 64 + (lane & 7) + ((lane >> 4) << 3);
    const int bAdd = (lane >> 3) & 1;

    void* outs[3] = {o0, o1, o2};
    for (int s = 0; s < nst; s++) {
        float c[2][8][4];
        #pragma unroll
        for (int mf = 0; mf < 2; mf++)
            #pragma unroll
            for (int nf = 0; nf < 8; nf++)
                #pragma unroll
                for (int t = 0; t < 4; t++) c[mf][nf][t] = 0.f;

        __syncthreads();
        {
            const uint4* src = (const uint4*)g_wimg[wbase + s];
            #pragma unroll
            for (int kk = 0; kk < 8; kk++)
                ((uint4*)Bs)[tid + kk * 256] = src[tid + kk * 256];
        }
        __syncthreads();
        #pragma unroll
        for (int ks = 0; ks < 8; ks++) {
            const int chA = 2 * ks + aAdd;
            const int chB = 2 * ks + bAdd;
            uint32_t Ah[2][4];
            #pragma unroll
            for (int mf = 0; mf < 2; mf++) {
                int row = rA + mf * 16;
                ldsm4(sbA + row * 256 + (((chA ^ (row & 7))) << 4), Ah[mf]);
            }
            #pragma unroll
            for (int nf16 = 0; nf16 < 4; nf16++) {
                int row = rB + nf16 * 16;
                uint32_t Bf[4];
                ldsm4(sbB + row * 256 + (((chB ^ (row & 7))) << 4), Bf);
                #pragma unroll
                for (int mf = 0; mf < 2; mf++) {
                    mma16816h(c[mf][2 * nf16],     Ah[mf], Bf[0], Bf[1]);
                    mma16816h(c[mf][2 * nf16 + 1], Ah[mf], Bf[2], Bf[3]);
                }
            }
        }

        // epilogue
        #pragma unroll
        for (int mf = 0; mf < 2; mf++) {
            int m0 = rowBase + warp_m * 32 + mf * 16 + (lane >> 2);
            #pragma unroll
            for (int nf = 0; nf < 8; nf++) {
                int n = warp_n * 64 + nf * 8 + ((lane & 3) << 1);
                float b0 = sbias[s * 128 + n], b1 = sbias[s * 128 + n + 1];
                if (OUTF16) {
                    __half2* O = (__half2*)outs[s];
                    if (m0 < nrows)
                        O[(size_t)m0 * 64 + (n >> 1)] =
                            __floats2half2_rn(c[mf][nf][0] + b0, c[mf][nf][1] + b1);
                    if (m0 + 8 < nrows)
                        O[(size_t)(m0 + 8) * 64 + (n >> 1)] =
                            __floats2half2_rn(c[mf][nf][2] + b0, c[mf][nf][3] + b1);
                } else {
                    float* O = (float*)outs[s];
                    if (m0 < nrows)
                        *(float2*)(O + (size_t)m0 * 128 + n) =
                            make_float2(c[mf][nf][0] + b0, c[mf][nf][1] + b1);
                    if (m0 + 8 < nrows)
                        *(float2*)(O + (size_t)(m0 + 8) * 128 + n) =
                            make_float2(c[mf][nf][2] + b0, c[mf][nf][3] + b1);
                }
            }
        }
    }
}

// ---------------- per-row attention (one warp per destination node) ---------
// q/k/v fp16 HEAD-MAJOR; mid fp16. Simple batch-4 loop (best config).
__global__ void k_attn(int n) {
    int gw = (blockIdx.x * blockDim.x + threadIdx.x) >> 5;
    int lane = threadIdx.x & 31;
    if (gw >= n) return;
    int s0 = g_start[gw], s1 = g_start[gw + 1];
    const __half* qh = (const __half*)g_q;
    const __half* kh = (const __half*)g_k;
    const __half* vh = (const __half*)g_v;

    uint2 qr = *(const uint2*)(qh + (size_t)gw * 128 + lane * 4);
    float2 q01 = __half22float2(*reinterpret_cast<__half2*>(&qr.x));
    float2 q23 = __half22float2(*reinterpret_cast<__half2*>(&qr.y));

    float a0 = 0.f, a1 = 0.f, a2 = 0.f, a3 = 0.f, s = 0.f;

    int e = s0;
    for (; e + 4 <= s1; e += 4) {
        int c0 = g_colsorted[e + 0];
        int c1 = g_colsorted[e + 1];
        int c2 = g_colsorted[e + 2];
        int c3 = g_colsorted[e + 3];
        uint2 kr0 = *(const uint2*)(kh + (size_t)c0 * 128 + lane * 4);
        uint2 kr1 = *(const uint2*)(kh + (size_t)c1 * 128 + lane * 4);
        uint2 kr2 = *(const uint2*)(kh + (size_t)c2 * 128 + lane * 4);
        uint2 kr3 = *(const uint2*)(kh + (size_t)c3 * 128 + lane * 4);
        uint2 vr0 = *(const uint2*)(vh + (size_t)c0 * 128 + lane * 4);
        uint2 vr1 = *(const uint2*)(vh + (size_t)c1 * 128 + lane * 4);
        uint2 vr2 = *(const uint2*)(vh + (size_t)c2 * 128 + lane * 4);
        uint2 vr3 = *(const uint2*)(vh + (size_t)c3 * 128 + lane * 4);

        uint2 krs[4] = {kr0, kr1, kr2, kr3};
        uint2 vrs[4] = {vr0, vr1, vr2, vr3};
        float p[4];
        #pragma unroll
        for (int j = 0; j < 4; j++) {
            float2 k01 = __half22float2(*reinterpret_cast<__half2*>(&krs[j].x));
            float2 k23 = __half22float2(*reinterpret_cast<__half2*>(&krs[j].y));
            float t = q01.x * k01.x;
            t = fmaf(q01.y, k01.y, t);
            t = fmaf(q23.x, k23.x, t);
            t = fmaf(q23.y, k23.y, t);
            p[j] = t;
        }
        #pragma unroll
        for (int j = 0; j < 4; j++) p[j] += __shfl_xor_sync(0xffffffffu, p[j], 1);
        #pragma unroll
        for (int j = 0; j < 4; j++) p[j] += __shfl_xor_sync(0xffffffffu, p[j], 2);
        #pragma unroll
        for (int j = 0; j < 4; j++) {
            float ex = __expf(p[j]);
            float2 v01 = __half22float2(*reinterpret_cast<__half2*>(&vrs[j].x));
            float2 v23 = __half22float2(*reinterpret_cast<__half2*>(&vrs[j].y));
            s += ex;
            a0 = fmaf(ex, v01.x, a0);
            a1 = fmaf(ex, v01.y, a1);
            a2 = fmaf(ex, v23.x, a2);
            a3 = fmaf(ex, v23.y, a3);
        }
    }
    for (; e < s1; e++) {
        int c = g_colsorted[e];
        uint2 kr = *(const uint2*)(kh + (size_t)c * 128 + lane * 4);
        uint2 vr = *(const uint2*)(vh + (size_t)c * 128 + lane * 4);
        float2 k01 = __half22float2(*reinterpret_cast<__half2*>(&kr.x));
        float2 k23 = __half22float2(*reinterpret_cast<__half2*>(&kr.y));
        float2 v01 = __half22float2(*reinterpret_cast<__half2*>(&vr.x));
        float2 v23 = __half22float2(*reinterpret_cast<__half2*>(&vr.y));
        float p = q01.x * k01.x;
        p = fmaf(q01.y, k01.y, p);
        p = fmaf(q23.x, k23.x, p);
        p = fmaf(q23.y, k23.y, p);
        p += __shfl_xor_sync(0xffffffffu, p, 1);
        p += __shfl_xor_sync(0xffffffffu, p, 2);
        float ex = __expf(p);
        s += ex;
        a0 = fmaf(ex, v01.x, a0);
        a1 = fmaf(ex, v01.y, a1);
        a2 = fmaf(ex, v23.x, a2);
        a3 = fmaf(ex, v23.y, a3);
    }
    float inv = (s > 0.f) ? 1.f / s : 0.f;
    __half2* mh = (__half2*)g_mid;
    mh[(size_t)gw * 64 + lane * 2 + 0] = __floats2half2_rn(a0 * inv, a1 * inv);
    mh[(size_t)gw * 64 + lane * 2 + 1] = __floats2half2_rn(a2 * inv, a3 * inv);
}

// ---------------- launch ------------------------------------------------------
extern "C" void kernel_launch(void* const* d_in, const int* in_sizes, int n_in,
                              void* d_out, int out_size) {
    const float* h    = (const float*)d_in[0];
    const void*  rowp = d_in[1];
    const void*  colp = d_in[2];
    const float* Wq = (const float*)d_in[3];
    const float* bq = (const float*)d_in[4];
    const float* Wk = (const float*)d_in[5];
    const float* bk = (const float*)d_in[6];
    const float* Wv = (const float*)d_in[7];
    const float* bv = (const float*)d_in[8];
    const float* Wo = (const float*)d_in[9];
    const float* bo = (const float*)d_in[10];
    float* out = (float*)d_out;

    int N = in_sizes[0] / HIDDEN;
    int E = in_sizes[1];

    cudaFuncSetAttribute((const void*)k_mma<true, false>,
                         cudaFuncAttributeMaxDynamicSharedMemorySize, SMEM_MMA);
    cudaFuncSetAttribute((const void*)k_mma<false, true>,
                         cudaFuncAttributeMaxDynamicSharedMemorySize, SMEM_MMA);

    void *pq, *pk, *pv, *pmid, *pcnt;
    cudaGetSymbolAddress(&pq, g_q);
    cudaGetSymbolAddress(&pk, g_k);
    cudaGetSymbolAddress(&pv, g_v);
    cudaGetSymbolAddress(&pmid, g_mid);
    cudaGetSymbolAddress(&pcnt, g_cnt);

    int gb = (N + 127) / 128;
    int nb = (N + 1 + 1023) / 1024;

    // One-time side stream + fork/join events (cached across capture).
    static cudaStream_t side = nullptr;
    static cudaEvent_t evFork = nullptr, evJoin = nullptr;
    if (!side) {
        cudaStreamCreateWithFlags(&side, cudaStreamNonBlocking);
        cudaEventCreateWithFlags(&evFork, cudaEventDisableTiming);
        cudaEventCreateWithFlags(&evJoin, cudaEventDisableTiming);
    }

    // main: memset -> (fork) wconv -> qkv -> (join) -> attn -> gemm_o
    // side:          hist -> scan -> scat
    cudaMemsetAsync(pcnt, 0, sizeof(g_cnt));
    cudaEventRecord(evFork, 0);
    cudaStreamWaitEvent(side, evFork, 0);
    k_hist<<<1024, 256, 0, side>>>(rowp, E);
    k_scan1<<<nb, 1024, 0, side>>>(N, E);
    k_scat<<<1024, 256, 0, side>>>(rowp, colp, E);
    cudaEventRecord(evJoin, side);

    k_wconv<<<128, 256>>>(Wq, bq, Wk, bk, Wv, bv, Wo, bo);
    k_mma<true, false><<<gb, 256, SMEM_MMA>>>(h, N, 0, 3, pq, pk, pv);

    cudaStreamWaitEvent(0, evJoin, 0);
    k_attn<<<(N + 7) / 8, 256>>>(N);
    k_mma<false, true><<<gb, 256, SMEM_MMA>>>(pmid, N, 3, 1, out, 0, 0);
}